// round 3
// baseline (speedup 1.0000x reference)
#include <cuda_runtime.h>
#include <cuda_bf16.h>
#include <mma.h>

using namespace nvcuda;

#define T_ 512
#define B_ 64
#define I_ 512
#define H_ 512
#define G_ 2048   // 4*H

// ---------------- scratch (device globals: allowed) ----------------
__device__ float    g_xproj[2ull * T_ * B_ * G_];   // [dir][t][b][4H]
__device__ float    g_h[2][2][B_][H_];              // [buf][dir][b][h]
__device__ unsigned g_bar[2];                       // per-direction barrier counter

// 3xTF32 split helpers (element-wise on wmma fragments)
#define SPLIT_FRAG(FH, FL, F)                                  \
    do {                                                        \
        _Pragma("unroll")                                       \
        for (int _e = 0; _e < (F).num_elements; _e++) {         \
            float _v  = (F).x[_e];                              \
            float _vh = wmma::__float_to_tf32(_v);              \
            (FH).x[_e] = _vh;                                   \
            (FL).x[_e] = wmma::__float_to_tf32(_v - _vh);       \
        }                                                       \
    } while (0)

// ---------------- init: reset barrier, seed h from h0 ----------------
__global__ void init_kernel(const float* __restrict__ h0)
{
    if (blockIdx.x == 0 && threadIdx.x < 2) g_bar[threadIdx.x] = 0u;
    int n = 2 * B_ * H_;
    for (int i = blockIdx.x * blockDim.x + threadIdx.x; i < n; i += gridDim.x * blockDim.x) {
        int d = i / (B_ * H_);
        int r = i % (B_ * H_);
        g_h[0][d][r / H_][r % H_] = h0[i];
    }
}

// ---------------- xproj: 3xTF32 wmma GEMM  [32768 x 2048 x 512], both dirs ----------------
__global__ void __launch_bounds__(256) xproj_kernel(
    const float* __restrict__ x,
    const float* __restrict__ Wf, const float* __restrict__ bf,
    const float* __restrict__ Wb, const float* __restrict__ bb)
{
    extern __shared__ float sm[];
    float* As = sm;              // [128][40]
    float* Bs = sm + 128 * 40;   // [64][40]

    const int dir = blockIdx.z;
    const float* W    = dir ? Wb : Wf;
    const float* bias = dir ? bb : bf;
    const size_t m0 = (size_t)blockIdx.y * 128;
    const int    n0 = blockIdx.x * 64;
    const int tid = threadIdx.x;
    const int wid = tid >> 5;
    const int row0 = (wid & 3) * 32;   // warp grid 4x2
    const int col0 = (wid >> 2) * 32;

    wmma::fragment<wmma::accumulator, 16, 16, 8, float> acc[2][2];
    #pragma unroll
    for (int i = 0; i < 2; i++)
        #pragma unroll
        for (int j = 0; j < 2; j++) wmma::fill_fragment(acc[i][j], 0.f);

    for (int k0 = 0; k0 < I_; k0 += 32) {
        __syncthreads();
        #pragma unroll
        for (int idx = tid; idx < 128 * 32; idx += 256) {
            int r = idx >> 5, c = idx & 31;
            As[r * 40 + c] = x[(m0 + r) * I_ + k0 + c];
        }
        #pragma unroll
        for (int idx = tid; idx < 64 * 32; idx += 256) {
            int r = idx >> 5, c = idx & 31;
            Bs[r * 40 + c] = W[(size_t)(n0 + r) * I_ + k0 + c];
        }
        __syncthreads();
        #pragma unroll
        for (int kk = 0; kk < 32; kk += 8) {
            wmma::fragment<wmma::matrix_a, 16, 16, 8, wmma::precision::tf32, wmma::row_major> a, ah[2], al[2];
            wmma::fragment<wmma::matrix_b, 16, 16, 8, wmma::precision::tf32, wmma::col_major> b, bh[2], bl[2];
            #pragma unroll
            for (int i = 0; i < 2; i++) {
                wmma::load_matrix_sync(a, As + (row0 + 16 * i) * 40 + kk, 40);
                SPLIT_FRAG(ah[i], al[i], a);
            }
            #pragma unroll
            for (int j = 0; j < 2; j++) {
                wmma::load_matrix_sync(b, Bs + (col0 + 16 * j) * 40 + kk, 40);
                SPLIT_FRAG(bh[j], bl[j], b);
            }
            #pragma unroll
            for (int i = 0; i < 2; i++)
                #pragma unroll
                for (int j = 0; j < 2; j++) {
                    wmma::mma_sync(acc[i][j], al[i], bh[j], acc[i][j]);
                    wmma::mma_sync(acc[i][j], ah[i], bl[j], acc[i][j]);
                    wmma::mma_sync(acc[i][j], ah[i], bh[j], acc[i][j]);
                }
        }
    }
    __syncthreads();
    float* Os = sm;  // [128][72]
    #pragma unroll
    for (int i = 0; i < 2; i++)
        #pragma unroll
        for (int j = 0; j < 2; j++)
            wmma::store_matrix_sync(Os + (row0 + 16 * i) * 72 + col0 + 16 * j, acc[i][j], 72,
                                    wmma::mem_row_major);
    __syncthreads();
    float* out = g_xproj + (size_t)dir * T_ * B_ * G_;
    #pragma unroll
    for (int idx = tid; idx < 128 * 64; idx += 256) {
        int r = idx >> 6, c = idx & 63;
        out[(m0 + r) * G_ + n0 + c] = Os[r * 72 + c] + bias[n0 + c];
    }
}

// ---------------- scan: persistent recurrent kernel (3xTF32) ----------------
#define NC 32   // CTAs per direction
#define HS 16   // H columns per CTA

__global__ void __launch_bounds__(256, 1) scan_kernel(
    const float* __restrict__ c0,
    const float* __restrict__ Whf, const float* __restrict__ Whb,
    float* __restrict__ out)
{
    extern __shared__ float sm[];
    float* Ws = sm;                  // [64][520]  W_hh slice (row c = gate column c of this CTA)
    float* hb = Ws + 64 * 520;       // [64][72]   h k-chunk
    float* gS = hb + 64 * 72;        // [64][72]   gates staging
    float* cS = gS + 64 * 72;        // [64*16]    cell state slice

    const int cta = blockIdx.x;
    const int dir = cta / NC;
    const int j   = cta % NC;
    const float* Wh = dir ? Whb : Whf;
    const float* xp = g_xproj + (size_t)dir * T_ * B_ * G_;
    const int tid = threadIdx.x;
    const int wid = tid >> 5;
    const int row0 = (wid & 3) * 16;   // warp tile 16x32 within 64x64 gate tile
    const int col0 = (wid >> 2) * 32;

    for (int idx = tid; idx < 64 * 512; idx += 256) {
        int c = idx >> 9, k = idx & 511;
        int wrow = (c >> 4) * H_ + j * HS + (c & 15);
        Ws[c * 520 + k] = Wh[(size_t)wrow * H_ + k];
    }
    for (int idx = tid; idx < 64 * HS; idx += 256) {
        int b = idx >> 4, cc = idx & 15;
        cS[idx] = c0[((size_t)dir * B_ + b) * H_ + j * HS + cc];
    }
    __syncthreads();

    for (int s = 0; s < T_; ++s) {
        const int cbuf = s & 1;
        const int t = dir ? (T_ - 1 - s) : s;
        const float* xpt = xp + (size_t)t * B_ * G_;

        wmma::fragment<wmma::accumulator, 16, 16, 8, float> acc[2];
        #pragma unroll
        for (int jn = 0; jn < 2; jn++) {
            int tc = col0 + 16 * jn;
            int gcol = (tc >> 4) * H_ + j * HS;
            wmma::load_matrix_sync(acc[jn], xpt + (size_t)row0 * G_ + gcol, G_, wmma::mem_row_major);
        }

        const float* hsrc = &g_h[cbuf][dir][0][0];
        for (int k0 = 0; k0 < H_; k0 += 64) {
            __syncthreads();
            #pragma unroll
            for (int idx = tid; idx < 64 * 64; idx += 256) {
                int r = idx >> 6, c = idx & 63;
                hb[r * 72 + c] = hsrc[r * H_ + k0 + c];
            }
            __syncthreads();
            #pragma unroll
            for (int kk = 0; kk < 64; kk += 8) {
                wmma::fragment<wmma::matrix_a, 16, 16, 8, wmma::precision::tf32, wmma::row_major> a, ah, al;
                wmma::load_matrix_sync(a, hb + row0 * 72 + kk, 72);
                SPLIT_FRAG(ah, al, a);
                #pragma unroll
                for (int jn = 0; jn < 2; jn++) {
                    wmma::fragment<wmma::matrix_b, 16, 16, 8, wmma::precision::tf32, wmma::col_major> b, bh, bl;
                    // FIX: B fragment must index the SAME K-chunk as A: k0 + kk (was: kk only)
                    wmma::load_matrix_sync(b, Ws + (col0 + 16 * jn) * 520 + k0 + kk, 520);
                    SPLIT_FRAG(bh, bl, b);
                    wmma::mma_sync(acc[jn], al, bh, acc[jn]);
                    wmma::mma_sync(acc[jn], ah, bl, acc[jn]);
                    wmma::mma_sync(acc[jn], ah, bh, acc[jn]);
                }
            }
        }
        __syncthreads();
        #pragma unroll
        for (int jn = 0; jn < 2; jn++)
            wmma::store_matrix_sync(gS + row0 * 72 + col0 + 16 * jn, acc[jn], 72, wmma::mem_row_major);
        __syncthreads();

        float* hdst = &g_h[cbuf ^ 1][dir][0][0];
        #pragma unroll
        for (int idx = tid; idx < 64 * HS; idx += 256) {
            int b = idx >> 4, cc = idx & 15;
            float gi = gS[b * 72 + cc];
            float gf = gS[b * 72 + 16 + cc];
            float gg = gS[b * 72 + 32 + cc];
            float go = gS[b * 72 + 48 + cc];
            float ii = 1.f / (1.f + expf(-gi));
            float ff = 1.f / (1.f + expf(-gf));
            float g2 = tanhf(gg);
            float oo = 1.f / (1.f + expf(-go));
            float cv = ff * cS[idx] + ii * g2;
            cS[idx] = cv;
            float hv = oo * tanhf(cv);
            hdst[b * H_ + j * HS + cc] = hv;
            out[((size_t)t * B_ + b) * (2 * H_) + dir * H_ + j * HS + cc] = hv;
        }
        __syncthreads();

        if (tid == 0) {
            __threadfence();
            atomicAdd(&g_bar[dir], 1u);
            unsigned target = (unsigned)(s + 1) * NC;
            volatile unsigned* p = &g_bar[dir];
            while (*p < target) __nanosleep(32);
            __threadfence();
        }
        __syncthreads();
    }
}

// ---------------- launch ----------------
extern "C" void kernel_launch(void* const* d_in, const int* in_sizes, int n_in,
                              void* d_out, int out_size)
{
    const float* x    = (const float*)d_in[0];
    const float* h0   = (const float*)d_in[1];
    const float* c0   = (const float*)d_in[2];
    const float* Wihf = (const float*)d_in[3];
    const float* Whhf = (const float*)d_in[4];
    const float* bf   = (const float*)d_in[5];
    const float* Wihb = (const float*)d_in[6];
    const float* Whhb = (const float*)d_in[7];
    const float* bb   = (const float*)d_in[8];
    float* out = (float*)d_out;

    cudaFuncSetAttribute(scan_kernel, cudaFuncAttributeMaxDynamicSharedMemorySize, 174080);

    init_kernel<<<32, 256>>>(h0);

    dim3 gx(G_ / 64, (T_ * B_) / 128, 2);
    xproj_kernel<<<gx, 256, 128 * 72 * sizeof(float)>>>(x, Wihf, bf, Wihb, bb);

    scan_kernel<<<64, 256, 174080>>>(c0, Whhf, Whhb, out);
}

// round 4
// speedup vs baseline: 1.2993x; 1.2993x over previous
#include <cuda_runtime.h>
#include <mma.h>

using namespace nvcuda;

#define T_ 512
#define B_ 64
#define I_ 512
#define H_ 512
#define G_ 2048   // 4*H

// ---------------- scratch (device globals: allowed) ----------------
__device__ float    g_xproj[2ull * T_ * B_ * G_];   // [dir][t][b][4H]
__device__ float    g_h[2][2][B_][H_];              // [buf][dir][b][h]
__device__ unsigned g_bar[2];

__device__ __forceinline__ void split_tf32(float v, float& hi, float& lo)
{
    hi = wmma::__float_to_tf32(v);
    lo = wmma::__float_to_tf32(v - hi);
}

// ---------------- init ----------------
__global__ void init_kernel(const float* __restrict__ h0)
{
    if (blockIdx.x == 0 && threadIdx.x < 2) g_bar[threadIdx.x] = 0u;
    int n = 2 * B_ * H_;
    for (int i = blockIdx.x * blockDim.x + threadIdx.x; i < n; i += gridDim.x * blockDim.x) {
        int d = i / (B_ * H_);
        int r = i % (B_ * H_);
        g_h[0][d][r / H_][r % H_] = h0[i];
    }
}

// ---------------- xproj: 3xTF32, split-at-fill, CTA 128x128 ----------------
__global__ void __launch_bounds__(256, 2) xproj_kernel(
    const float* __restrict__ x,
    const float* __restrict__ Wf, const float* __restrict__ Wb)
{
    extern __shared__ float sm[];
    float* Ah = sm;                // [128][40]
    float* Al = Ah + 128 * 40;
    float* Bh = Al + 128 * 40;
    float* Bl = Bh + 128 * 40;

    const int dir = blockIdx.z;
    const float* W = dir ? Wb : Wf;
    const size_t m0 = (size_t)blockIdx.y * 128;
    const int    n0 = blockIdx.x * 128;
    const int tid = threadIdx.x;
    const int wid = tid >> 5;
    const int row0 = (wid & 3) * 32;   // warp grid 4(M) x 2(N), warp tile 32x64
    const int col0 = (wid >> 2) * 64;

    wmma::fragment<wmma::accumulator, 16, 16, 8, float> acc[2][4];
    #pragma unroll
    for (int i = 0; i < 2; i++)
        #pragma unroll
        for (int j = 0; j < 4; j++) wmma::fill_fragment(acc[i][j], 0.f);

    for (int k0 = 0; k0 < I_; k0 += 32) {
        __syncthreads();
        // fill A (128x32) and B (128x32), splitting once per element
        #pragma unroll
        for (int it = 0; it < 4; it++) {
            int f = tid + it * 256;          // 0..1023 float4 slots
            int r = f >> 3, c4 = f & 7;
            float4 v = *(const float4*)&x[(m0 + r) * I_ + k0 + c4 * 4];
            float4 vh, vl;
            split_tf32(v.x, vh.x, vl.x); split_tf32(v.y, vh.y, vl.y);
            split_tf32(v.z, vh.z, vl.z); split_tf32(v.w, vh.w, vl.w);
            *(float4*)&Ah[r * 40 + c4 * 4] = vh;
            *(float4*)&Al[r * 40 + c4 * 4] = vl;
        }
        #pragma unroll
        for (int it = 0; it < 4; it++) {
            int f = tid + it * 256;
            int r = f >> 3, c4 = f & 7;
            float4 v = *(const float4*)&W[(size_t)(n0 + r) * I_ + k0 + c4 * 4];
            float4 vh, vl;
            split_tf32(v.x, vh.x, vl.x); split_tf32(v.y, vh.y, vl.y);
            split_tf32(v.z, vh.z, vl.z); split_tf32(v.w, vh.w, vl.w);
            *(float4*)&Bh[r * 40 + c4 * 4] = vh;
            *(float4*)&Bl[r * 40 + c4 * 4] = vl;
        }
        __syncthreads();
        #pragma unroll
        for (int kk = 0; kk < 32; kk += 8) {
            wmma::fragment<wmma::matrix_a, 16, 16, 8, wmma::precision::tf32, wmma::row_major> a_h[2], a_l[2];
            #pragma unroll
            for (int i = 0; i < 2; i++) {
                wmma::load_matrix_sync(a_h[i], Ah + (row0 + 16 * i) * 40 + kk, 40);
                wmma::load_matrix_sync(a_l[i], Al + (row0 + 16 * i) * 40 + kk, 40);
            }
            #pragma unroll
            for (int j = 0; j < 4; j++) {
                wmma::fragment<wmma::matrix_b, 16, 16, 8, wmma::precision::tf32, wmma::col_major> b_h, b_l;
                wmma::load_matrix_sync(b_h, Bh + (col0 + 16 * j) * 40 + kk, 40);
                wmma::load_matrix_sync(b_l, Bl + (col0 + 16 * j) * 40 + kk, 40);
                #pragma unroll
                for (int i = 0; i < 2; i++) {
                    wmma::mma_sync(acc[i][j], a_l[i], b_h, acc[i][j]);
                    wmma::mma_sync(acc[i][j], a_h[i], b_l, acc[i][j]);
                    wmma::mma_sync(acc[i][j], a_h[i], b_h, acc[i][j]);
                }
            }
        }
    }
    // epilogue: store fragments straight to global (bias folded into scan)
    float* outp = g_xproj + (size_t)dir * T_ * B_ * G_;
    #pragma unroll
    for (int i = 0; i < 2; i++)
        #pragma unroll
        for (int j = 0; j < 4; j++)
            wmma::store_matrix_sync(outp + (m0 + row0 + 16 * i) * G_ + n0 + col0 + 16 * j,
                                    acc[i][j], G_, wmma::mem_row_major);
}

// ---------------- scan: persistent, 64 CTAs/dir, 8 H-cols per CTA ----------------
#define NCPD 64
#define HS 8

#define HB_H(buf) (hb + (buf) * (2 * 64 * 72))
#define HB_L(buf) (hb + (buf) * (2 * 64 * 72) + 64 * 72)

__global__ void __launch_bounds__(256, 1) scan_kernel(
    const float* __restrict__ c0,
    const float* __restrict__ Whf, const float* __restrict__ Whb,
    const float* __restrict__ bf,  const float* __restrict__ bb,
    float* __restrict__ out)
{
    extern __shared__ float sm[];
    float* Wh_s = sm;                       // [32][520] hi
    float* Wl_s = Wh_s + 32 * 520;          // [32][520] lo
    float* hb   = Wl_s + 32 * 520;          // 2 bufs x (hi,lo) x [64][72]
    float* gS   = hb + 2 * 2 * 64 * 72;     // [64][40]
    float* cS   = gS + 64 * 40;             // [64][8]
    float* bias_s = cS + 64 * 8;            // [32]

    const int cta = blockIdx.x;
    const int dir = cta / NCPD;
    const int j   = cta % NCPD;
    const float* Wh   = dir ? Whb : Whf;
    const float* bias = dir ? bb : bf;
    const float* xp = g_xproj + (size_t)dir * T_ * B_ * G_;
    const int tid = threadIdx.x;
    const int wid = tid >> 5;
    const int row0 = (wid & 3) * 16;   // warp grid 4(M) x 2(N), warp tile 16x16
    const int col0 = (wid >> 2) * 16;

    // W_hh slice, split once: tile col c -> W row (c/8)*H + j*8 + (c%8)
    for (int idx = tid; idx < 32 * 512; idx += 256) {
        int c = idx >> 9, k = idx & 511;
        int wrow = (c >> 3) * H_ + j * HS + (c & 7);
        float v = Wh[(size_t)wrow * H_ + k];
        float hi, lo; split_tf32(v, hi, lo);
        Wh_s[c * 520 + k] = hi;
        Wl_s[c * 520 + k] = lo;
    }
    if (tid < 32)
        bias_s[tid] = bias[(tid >> 3) * H_ + j * HS + (tid & 7)];
    for (int idx = tid; idx < 64 * HS; idx += 256)
        cS[idx] = c0[((size_t)dir * B_ + (idx >> 3)) * H_ + j * HS + (idx & 7)];
    __syncthreads();

    for (int s = 0; s < T_; ++s) {
        const int cbuf = s & 1;
        const int t = dir ? (T_ - 1 - s) : s;
        const float* hsrc = &g_h[cbuf][dir][0][0];

        wmma::fragment<wmma::accumulator, 16, 16, 8, float> acc;
        wmma::fill_fragment(acc, 0.f);

        // prefetch chunk 0 (k = 0..63) into buf 0
        {
            #pragma unroll
            for (int q = 0; q < 4; q++) {
                int f = tid + q * 256;           // 1024 float4 = 64 rows x 16
                int r = f >> 4, c4 = f & 15;
                float4 v = *(const float4*)&hsrc[r * H_ + c4 * 4];
                float4 vh, vl;
                split_tf32(v.x, vh.x, vl.x); split_tf32(v.y, vh.y, vl.y);
                split_tf32(v.z, vh.z, vl.z); split_tf32(v.w, vh.w, vl.w);
                *(float4*)&HB_H(0)[r * 72 + c4 * 4] = vh;
                *(float4*)&HB_L(0)[r * 72 + c4 * 4] = vl;
            }
        }
        __syncthreads();

        for (int ch = 0; ch < 8; ch++) {
            // register-prefetch next chunk
            float4 pf[4];
            if (ch < 7) {
                int k0n = (ch + 1) * 64;
                #pragma unroll
                for (int q = 0; q < 4; q++) {
                    int f = tid + q * 256;
                    int r = f >> 4, c4 = f & 15;
                    pf[q] = *(const float4*)&hsrc[r * H_ + k0n + c4 * 4];
                }
            }
            // MMA on current buffer
            const float* Hh = HB_H(ch & 1);
            const float* Hl = HB_L(ch & 1);
            #pragma unroll
            for (int kk = 0; kk < 64; kk += 8) {
                wmma::fragment<wmma::matrix_a, 16, 16, 8, wmma::precision::tf32, wmma::row_major> a_h, a_l;
                wmma::fragment<wmma::matrix_b, 16, 16, 8, wmma::precision::tf32, wmma::col_major> b_h, b_l;
                wmma::load_matrix_sync(a_h, Hh + row0 * 72 + kk, 72);
                wmma::load_matrix_sync(a_l, Hl + row0 * 72 + kk, 72);
                wmma::load_matrix_sync(b_h, Wh_s + col0 * 520 + ch * 64 + kk, 520);
                wmma::load_matrix_sync(b_l, Wl_s + col0 * 520 + ch * 64 + kk, 520);
                wmma::mma_sync(acc, a_l, b_h, acc);
                wmma::mma_sync(acc, a_h, b_l, acc);
                wmma::mma_sync(acc, a_h, b_h, acc);
            }
            // store prefetched chunk (split at fill)
            if (ch < 7) {
                float* Nh = HB_H((ch + 1) & 1);
                float* Nl = HB_L((ch + 1) & 1);
                #pragma unroll
                for (int q = 0; q < 4; q++) {
                    int f = tid + q * 256;
                    int r = f >> 4, c4 = f & 15;
                    float4 vh, vl;
                    split_tf32(pf[q].x, vh.x, vl.x); split_tf32(pf[q].y, vh.y, vl.y);
                    split_tf32(pf[q].z, vh.z, vl.z); split_tf32(pf[q].w, vh.w, vl.w);
                    *(float4*)&Nh[r * 72 + c4 * 4] = vh;
                    *(float4*)&Nl[r * 72 + c4 * 4] = vl;
                }
            }
            __syncthreads();
        }

        wmma::store_matrix_sync(gS + row0 * 40 + col0, acc, 40, wmma::mem_row_major);
        __syncthreads();

        // elementwise LSTM cell; adds x_proj + bias here
        float* hdst = &g_h[cbuf ^ 1][dir][0][0];
        const float* xpt = xp + (size_t)t * B_ * G_;
        #pragma unroll
        for (int idx = tid; idx < 64 * HS; idx += 256) {
            int b = idx >> 3, cc = idx & 7;
            const float* xrow = xpt + (size_t)b * G_ + j * HS + cc;
            float gi = gS[b * 40 +      cc] + xrow[0]        + bias_s[     cc];
            float gf = gS[b * 40 +  8 + cc] + xrow[H_]       + bias_s[ 8 + cc];
            float gg = gS[b * 40 + 16 + cc] + xrow[2 * H_]   + bias_s[16 + cc];
            float go = gS[b * 40 + 24 + cc] + xrow[3 * H_]   + bias_s[24 + cc];
            float ii = 1.f / (1.f + expf(-gi));
            float ff = 1.f / (1.f + expf(-gf));
            float g2 = tanhf(gg);
            float oo = 1.f / (1.f + expf(-go));
            float cv = ff * cS[idx] + ii * g2;
            cS[idx] = cv;
            float hv = oo * tanhf(cv);
            hdst[b * H_ + j * HS + cc] = hv;
            out[((size_t)t * B_ + b) * (2 * H_) + dir * H_ + j * HS + cc] = hv;
        }
        __syncthreads();

        // grid barrier within this direction
        if (tid == 0) {
            __threadfence();
            atomicAdd(&g_bar[dir], 1u);
            unsigned target = (unsigned)(s + 1) * NCPD;
            volatile unsigned* p = &g_bar[dir];
            while (*p < target) __nanosleep(32);
            __threadfence();
        }
        __syncthreads();
    }
}

// ---------------- launch ----------------
extern "C" void kernel_launch(void* const* d_in, const int* in_sizes, int n_in,
                              void* d_out, int out_size)
{
    const float* x    = (const float*)d_in[0];
    const float* h0   = (const float*)d_in[1];
    const float* c0   = (const float*)d_in[2];
    const float* Wihf = (const float*)d_in[3];
    const float* Whhf = (const float*)d_in[4];
    const float* bf   = (const float*)d_in[5];
    const float* Wihb = (const float*)d_in[6];
    const float* Whhb = (const float*)d_in[7];
    const float* bb   = (const float*)d_in[8];
    float* out = (float*)d_out;

    // scan smem: (2*32*520 + 2*2*64*72 + 64*40 + 64*8 + 32) * 4 = 219264 B
    cudaFuncSetAttribute(scan_kernel, cudaFuncAttributeMaxDynamicSharedMemorySize, 219264);
    // xproj smem: 4 * 128*40 * 4 = 81920 B
    cudaFuncSetAttribute(xproj_kernel, cudaFuncAttributeMaxDynamicSharedMemorySize, 81920);

    init_kernel<<<32, 256>>>(h0);

    dim3 gx(G_ / 128, (T_ * B_) / 128, 2);
    xproj_kernel<<<gx, 256, 81920>>>(x, Wihf, Wihb);

    scan_kernel<<<128, 256, 219264>>>(c0, Whhf, Whhb, bf, bb, out);
}

// round 5
// speedup vs baseline: 1.7914x; 1.3788x over previous
#include <cuda_runtime.h>
#include <mma.h>

using namespace nvcuda;

#define T_ 512
#define B_ 64
#define I_ 512
#define H_ 512
#define G_ 2048   // 4*H

// ---------------- scratch (device globals: allowed) ----------------
__device__ float    g_xproj[2ull * T_ * B_ * G_];   // [dir][t][b][4H]
__device__ float    g_h[2][2][B_][H_];              // [buf][dir][b][h]
__device__ unsigned g_bar[2];

// Dekker split for tf32: hi = v truncated to tf32 mantissa, lo = v - hi (exact in fp32).
// HMMA reads the top 19 bits of each operand register, so passing lo un-rounded is fine
// (residual ~2^-26).
__device__ __forceinline__ float tf32_hi(float v)
{
    return __int_as_float(__float_as_int(v) & 0xFFFFE000);
}

// ---------------- xproj: 3xTF32, split-at-fill, CTA 128x128; also does init ----------------
__global__ void __launch_bounds__(256, 2) xproj_kernel(
    const float* __restrict__ x,
    const float* __restrict__ Wf, const float* __restrict__ Wb,
    const float* __restrict__ h0)
{
    extern __shared__ float sm[];
    float* Ah = sm;                // [128][36]  (stride 36 ≡ 4 mod 32: conflict-free)
    float* Al = Ah + 128 * 36;
    float* Bh = Al + 128 * 36;
    float* Bl = Bh + 128 * 36;

    const int tid = threadIdx.x;

    // ---- init fold: one CTA seeds g_h[0] from h0 and resets the grid barrier ----
    if (blockIdx.x == 0 && blockIdx.y == 0 && blockIdx.z == 0) {
        if (tid < 2) g_bar[tid] = 0u;
        float* gh0 = &g_h[0][0][0][0];
        #pragma unroll 4
        for (int i = tid; i < 2 * B_ * H_; i += 256) gh0[i] = h0[i];
    }

    const int dir = blockIdx.z;
    const float* W = dir ? Wb : Wf;
    const size_t m0 = (size_t)blockIdx.y * 128;
    const int    n0 = blockIdx.x * 128;
    const int wid = tid >> 5;
    const int row0 = (wid & 3) * 32;   // warp grid 4(M) x 2(N), warp tile 32x64
    const int col0 = (wid >> 2) * 64;

    wmma::fragment<wmma::accumulator, 16, 16, 8, float> acc[2][4];
    #pragma unroll
    for (int i = 0; i < 2; i++)
        #pragma unroll
        for (int j = 0; j < 4; j++) wmma::fill_fragment(acc[i][j], 0.f);

    for (int k0 = 0; k0 < I_; k0 += 32) {
        __syncthreads();
        #pragma unroll
        for (int it = 0; it < 4; it++) {
            int f = tid + it * 256;          // 1024 float4 slots: 128 rows x 8
            int r = f >> 3, c4 = f & 7;
            float4 v = *(const float4*)&x[(m0 + r) * I_ + k0 + c4 * 4];
            float4 vh, vl;
            vh.x = tf32_hi(v.x); vl.x = v.x - vh.x;
            vh.y = tf32_hi(v.y); vl.y = v.y - vh.y;
            vh.z = tf32_hi(v.z); vl.z = v.z - vh.z;
            vh.w = tf32_hi(v.w); vl.w = v.w - vh.w;
            *(float4*)&Ah[r * 36 + c4 * 4] = vh;
            *(float4*)&Al[r * 36 + c4 * 4] = vl;
        }
        #pragma unroll
        for (int it = 0; it < 4; it++) {
            int f = tid + it * 256;
            int r = f >> 3, c4 = f & 7;
            float4 v = *(const float4*)&W[(size_t)(n0 + r) * I_ + k0 + c4 * 4];
            float4 vh, vl;
            vh.x = tf32_hi(v.x); vl.x = v.x - vh.x;
            vh.y = tf32_hi(v.y); vl.y = v.y - vh.y;
            vh.z = tf32_hi(v.z); vl.z = v.z - vh.z;
            vh.w = tf32_hi(v.w); vl.w = v.w - vh.w;
            *(float4*)&Bh[r * 36 + c4 * 4] = vh;
            *(float4*)&Bl[r * 36 + c4 * 4] = vl;
        }
        __syncthreads();
        #pragma unroll
        for (int kk = 0; kk < 32; kk += 8) {
            wmma::fragment<wmma::matrix_a, 16, 16, 8, wmma::precision::tf32, wmma::row_major> a_h[2], a_l[2];
            #pragma unroll
            for (int i = 0; i < 2; i++) {
                wmma::load_matrix_sync(a_h[i], Ah + (row0 + 16 * i) * 36 + kk, 36);
                wmma::load_matrix_sync(a_l[i], Al + (row0 + 16 * i) * 36 + kk, 36);
            }
            #pragma unroll
            for (int j = 0; j < 4; j++) {
                wmma::fragment<wmma::matrix_b, 16, 16, 8, wmma::precision::tf32, wmma::col_major> b_h, b_l;
                wmma::load_matrix_sync(b_h, Bh + (col0 + 16 * j) * 36 + kk, 36);
                wmma::load_matrix_sync(b_l, Bl + (col0 + 16 * j) * 36 + kk, 36);
                #pragma unroll
                for (int i = 0; i < 2; i++) {
                    wmma::mma_sync(acc[i][j], a_l[i], b_h, acc[i][j]);
                    wmma::mma_sync(acc[i][j], a_h[i], b_l, acc[i][j]);
                    wmma::mma_sync(acc[i][j], a_h[i], b_h, acc[i][j]);
                }
            }
        }
    }
    float* outp = g_xproj + (size_t)dir * T_ * B_ * G_;
    #pragma unroll
    for (int i = 0; i < 2; i++)
        #pragma unroll
        for (int j = 0; j < 4; j++)
            wmma::store_matrix_sync(outp + (m0 + row0 + 16 * i) * G_ + n0 + col0 + 16 * j,
                                    acc[i][j], G_, wmma::mem_row_major);
}

// ---------------- scan: persistent; W fragments live in registers ----------------
// 64 CTAs/dir, HS=8 gate cols per CTA (tile M=64 batch x N=32 gates x K=512).
// Warp w owns K-slice [64w, 64w+64); its W hi/lo fragments are built ONCE.
// Per step: partial products per warp -> SMEM reduction -> LSTM cell.
#define NCPD 64
#define HS 8

__global__ void __launch_bounds__(256, 1) scan_kernel(
    const float* __restrict__ c0,
    const float* __restrict__ Whf, const float* __restrict__ Whb,
    const float* __restrict__ bf,  const float* __restrict__ bb,
    float* __restrict__ out)
{
    extern __shared__ float sm[];
    float* hS   = sm;                   // [64][516] fp32 h (stride 516 ≡ 4 mod 32)
    float* red  = hS + 64 * 516;        // [8][64][36] warp partials; aliases W staging
    float* cS   = red + 8 * 64 * 36;    // [64][8]
    float* bias_s = cS + 64 * 8;        // [32]

    const int cta = blockIdx.x;
    const int dir = cta / NCPD;
    const int j   = cta % NCPD;
    const float* Wh   = dir ? Whb : Whf;
    const float* bias = dir ? bb : bf;
    const float* xp = g_xproj + (size_t)dir * T_ * B_ * G_;
    const int tid = threadIdx.x;
    const int w   = tid >> 5;

    // ---- prologue: stage W slice (fp32) in SMEM (aliased with red), build register frags ----
    float* stage = red;                 // [32][516]
    #pragma unroll
    for (int q = 0; q < 16; q++) {
        int slot = tid + q * 256;       // 4096 float4: 32 rows x 128
        int r = slot >> 7, c4 = slot & 127;
        int wrow = (r >> 3) * H_ + j * HS + (r & 7);
        *(float4*)&stage[r * 516 + c4 * 4] = *(const float4*)&Wh[(size_t)wrow * H_ + c4 * 4];
    }
    if (tid < 32)
        bias_s[tid] = bias[(tid >> 3) * H_ + j * HS + (tid & 7)];
    #pragma unroll
    for (int idx = tid; idx < 64 * HS; idx += 256)
        cS[idx] = c0[((size_t)dir * B_ + (idx >> 3)) * H_ + j * HS + (idx & 7)];
    __syncthreads();

    wmma::fragment<wmma::matrix_b, 16, 16, 8, wmma::precision::tf32, wmma::col_major> bW_h[2][8], bW_l[2][8];
    #pragma unroll
    for (int j2 = 0; j2 < 2; j2++)
        #pragma unroll
        for (int t = 0; t < 8; t++) {
            wmma::fragment<wmma::matrix_b, 16, 16, 8, wmma::precision::tf32, wmma::col_major> fb;
            wmma::load_matrix_sync(fb, stage + (j2 * 16) * 516 + w * 64 + t * 8, 516);
            #pragma unroll
            for (int e = 0; e < fb.num_elements; e++) {
                float v = fb.x[e];
                float hi = tf32_hi(v);
                bW_h[j2][t].x[e] = hi;
                bW_l[j2][t].x[e] = v - hi;
            }
        }
    __syncthreads();   // all warps done reading stage; red region now free

    for (int s = 0; s < T_; ++s) {
        const int cbuf = s & 1;
        const int t = dir ? (T_ - 1 - s) : s;
        const float* hsrc = &g_h[cbuf][dir][0][0];
        const float* xpt = xp + (size_t)t * B_ * G_;

        // prefetch this thread's x_proj gate values (used in the cell phase)
        float xg[2][4];
        #pragma unroll
        for (int q = 0; q < 2; q++) {
            int p = tid + q * 256;
            int b = p >> 3, hc = p & 7;
            #pragma unroll
            for (int g = 0; g < 4; g++)
                xg[q][g] = xpt[(size_t)b * G_ + g * H_ + j * HS + hc];
        }

        // fill hS (fp32, 64x512) from global
        #pragma unroll
        for (int q = 0; q < 32; q++) {
            int slot = tid + q * 256;   // 8192 float4: 64 rows x 128
            int r = slot >> 7, c4 = slot & 127;
            *(float4*)&hS[r * 516 + c4 * 4] = *(const float4*)&hsrc[r * H_ + c4 * 4];
        }
        __syncthreads();

        // MMA: warp w sums over its K-slice; split A on the fly
        #pragma unroll
        for (int i = 0; i < 4; i++) {
            wmma::fragment<wmma::accumulator, 16, 16, 8, float> acc2[2];
            wmma::fill_fragment(acc2[0], 0.f);
            wmma::fill_fragment(acc2[1], 0.f);
            #pragma unroll
            for (int t8 = 0; t8 < 8; t8++) {
                wmma::fragment<wmma::matrix_a, 16, 16, 8, wmma::precision::tf32, wmma::row_major> fa, a_h, a_l;
                wmma::load_matrix_sync(fa, hS + (i * 16) * 516 + w * 64 + t8 * 8, 516);
                #pragma unroll
                for (int e = 0; e < fa.num_elements; e++) {
                    float v = fa.x[e];
                    float hi = tf32_hi(v);
                    a_h.x[e] = hi;
                    a_l.x[e] = v - hi;
                }
                #pragma unroll
                for (int j2 = 0; j2 < 2; j2++) {
                    wmma::mma_sync(acc2[j2], a_l, bW_h[j2][t8], acc2[j2]);
                    wmma::mma_sync(acc2[j2], a_h, bW_l[j2][t8], acc2[j2]);
                    wmma::mma_sync(acc2[j2], a_h, bW_h[j2][t8], acc2[j2]);
                }
            }
            #pragma unroll
            for (int j2 = 0; j2 < 2; j2++)
                wmma::store_matrix_sync(red + w * 2304 + (i * 16) * 36 + j2 * 16,
                                        acc2[j2], 36, wmma::mem_row_major);
        }
        __syncthreads();

        // reduce 8 warp partials + LSTM cell
        float* hdst = &g_h[cbuf ^ 1][dir][0][0];
        #pragma unroll
        for (int q = 0; q < 2; q++) {
            int p = tid + q * 256;
            int b = p >> 3, hc = p & 7;
            float sum[4];
            #pragma unroll
            for (int g = 0; g < 4; g++) {
                float s0 = 0.f;
                #pragma unroll
                for (int ww = 0; ww < 8; ww++)
                    s0 += red[ww * 2304 + b * 36 + g * 8 + hc];
                sum[g] = s0 + xg[q][g] + bias_s[g * 8 + hc];
            }
            float ii = 1.f / (1.f + expf(-sum[0]));
            float ff = 1.f / (1.f + expf(-sum[1]));
            float g2 = tanhf(sum[2]);
            float oo = 1.f / (1.f + expf(-sum[3]));
            float cv = ff * cS[p] + ii * g2;
            cS[p] = cv;
            float hv = oo * tanhf(cv);
            hdst[b * H_ + j * HS + hc] = hv;
            out[((size_t)t * B_ + b) * (2 * H_) + dir * H_ + j * HS + hc] = hv;
        }
        __syncthreads();

        // grid barrier within this direction
        if (tid == 0) {
            __threadfence();
            atomicAdd(&g_bar[dir], 1u);
            unsigned target = (unsigned)(s + 1) * NCPD;
            volatile unsigned* p = &g_bar[dir];
            while (*p < target) __nanosleep(32);
            __threadfence();
        }
        __syncthreads();
    }
}

// ---------------- launch ----------------
extern "C" void kernel_launch(void* const* d_in, const int* in_sizes, int n_in,
                              void* d_out, int out_size)
{
    const float* x    = (const float*)d_in[0];
    const float* h0   = (const float*)d_in[1];
    const float* c0   = (const float*)d_in[2];
    const float* Wihf = (const float*)d_in[3];
    const float* Whhf = (const float*)d_in[4];
    const float* bf   = (const float*)d_in[5];
    const float* Wihb = (const float*)d_in[6];
    const float* Whhb = (const float*)d_in[7];
    const float* bb   = (const float*)d_in[8];
    float* out = (float*)d_out;

    // scan smem: (64*516 + 8*64*36 + 64*8 + 32) * 4 = 208000 B
    cudaFuncSetAttribute(scan_kernel, cudaFuncAttributeMaxDynamicSharedMemorySize, 208000);
    // xproj smem: 4 * 128*36 * 4 = 73728 B
    cudaFuncSetAttribute(xproj_kernel, cudaFuncAttributeMaxDynamicSharedMemorySize, 73728);

    dim3 gx(G_ / 128, (T_ * B_) / 128, 2);
    xproj_kernel<<<gx, 256, 73728>>>(x, Wihf, Wihb, h0);

    scan_kernel<<<128, 256, 208000>>>(c0, Whhf, Whhb, bf, bb, out);
}

// round 6
// speedup vs baseline: 3.5872x; 2.0024x over previous
#include <cuda_runtime.h>
#include <cuda_fp16.h>
#include <mma.h>

using namespace nvcuda;

#define T_ 512
#define B_ 64
#define I_ 512
#define H_ 512
#define G_ 2048   // 4*H

#define LO_SCALE   2048.f
#define LO_INV     4.8828125e-4f   // 1/2048

// ---------------- scratch (device globals: allowed) ----------------
__device__ float    g_xproj[2ull * T_ * B_ * G_];   // [dir][t][b][4H]
__device__ __half   g_hh[2][2][B_][H_];             // h split hi   [buf][dir][b][h]
__device__ __half   g_hl[2][2][B_][H_];             // h split lo * 2048
__device__ unsigned g_bar[2];

// Split fp32 -> fp16 hi + scaled fp16 lo. hi = RN(v); lo = RN((v - hi) * 2048).
// v - hi is exact in fp32; scaling keeps lo in the fp16 normal range.
__device__ __forceinline__ void split_h16(float v, __half& hi, __half& lo)
{
    hi = __float2half_rn(v);
    lo = __float2half_rn((v - __half2float(hi)) * LO_SCALE);
}

// ---------------- xproj: 3xFP16, split-at-fill, CTA 128x64; also does init ----------------
__global__ void __launch_bounds__(256, 2) xproj_kernel(
    const float* __restrict__ x,
    const float* __restrict__ Wf, const float* __restrict__ Wb,
    const float* __restrict__ h0)
{
    extern __shared__ __align__(16) char smraw[];
    __half* Ah = (__half*)smraw;          // [128][72]
    __half* Al = Ah + 128 * 72;
    __half* Bh = Al + 128 * 72;           // [64][72]
    __half* Bl = Bh + 64 * 72;

    const int tid = threadIdx.x;

    // ---- init fold: one CTA seeds split h state and resets the grid barrier ----
    if (blockIdx.x == 0 && blockIdx.y == 0 && blockIdx.z == 0) {
        if (tid < 2) g_bar[tid] = 0u;
        __half* hh = &g_hh[0][0][0][0];
        __half* hl = &g_hl[0][0][0][0];
        #pragma unroll 4
        for (int i = tid; i < 2 * B_ * H_; i += 256) {
            __half hi, lo;
            split_h16(h0[i], hi, lo);
            hh[i] = hi; hl[i] = lo;
        }
    }

    const int dir = blockIdx.z;
    const float* W = dir ? Wb : Wf;
    const size_t m0 = (size_t)blockIdx.y * 128;
    const int    n0 = blockIdx.x * 64;
    const int wid = tid >> 5;
    const int row0 = (wid & 3) * 32;   // warp grid 4(M) x 2(N), warp tile 32x32
    const int col0 = (wid >> 2) * 32;

    wmma::fragment<wmma::accumulator, 16, 16, 16, float> am[2][2], ac[2][2];
    #pragma unroll
    for (int i = 0; i < 2; i++)
        #pragma unroll
        for (int j = 0; j < 2; j++) { wmma::fill_fragment(am[i][j], 0.f); wmma::fill_fragment(ac[i][j], 0.f); }

    for (int k0 = 0; k0 < I_; k0 += 64) {
        __syncthreads();
        #pragma unroll
        for (int it = 0; it < 8; it++) {
            int f = tid + it * 256;          // 2048 float4: 128 rows x 16
            int r = f >> 4, c4 = f & 15;
            float4 v = *(const float4*)&x[(m0 + r) * I_ + k0 + c4 * 4];
            __half hx, lx, hy, ly, hz, lz, hw, lw;
            split_h16(v.x, hx, lx); split_h16(v.y, hy, ly);
            split_h16(v.z, hz, lz); split_h16(v.w, hw, lw);
            *(__half2*)&Ah[r * 72 + c4 * 4]     = __halves2half2(hx, hy);
            *(__half2*)&Ah[r * 72 + c4 * 4 + 2] = __halves2half2(hz, hw);
            *(__half2*)&Al[r * 72 + c4 * 4]     = __halves2half2(lx, ly);
            *(__half2*)&Al[r * 72 + c4 * 4 + 2] = __halves2half2(lz, lw);
        }
        #pragma unroll
        for (int it = 0; it < 4; it++) {
            int f = tid + it * 256;          // 1024 float4: 64 rows x 16
            int r = f >> 4, c4 = f & 15;
            float4 v = *(const float4*)&W[(size_t)(n0 + r) * I_ + k0 + c4 * 4];
            __half hx, lx, hy, ly, hz, lz, hw, lw;
            split_h16(v.x, hx, lx); split_h16(v.y, hy, ly);
            split_h16(v.z, hz, lz); split_h16(v.w, hw, lw);
            *(__half2*)&Bh[r * 72 + c4 * 4]     = __halves2half2(hx, hy);
            *(__half2*)&Bh[r * 72 + c4 * 4 + 2] = __halves2half2(hz, hw);
            *(__half2*)&Bl[r * 72 + c4 * 4]     = __halves2half2(lx, ly);
            *(__half2*)&Bl[r * 72 + c4 * 4 + 2] = __halves2half2(lz, lw);
        }
        __syncthreads();
        #pragma unroll
        for (int kk = 0; kk < 64; kk += 16) {
            wmma::fragment<wmma::matrix_a, 16, 16, 16, __half, wmma::row_major> a_h[2], a_l[2];
            #pragma unroll
            for (int i = 0; i < 2; i++) {
                wmma::load_matrix_sync(a_h[i], Ah + (row0 + 16 * i) * 72 + kk, 72);
                wmma::load_matrix_sync(a_l[i], Al + (row0 + 16 * i) * 72 + kk, 72);
            }
            #pragma unroll
            for (int j = 0; j < 2; j++) {
                wmma::fragment<wmma::matrix_b, 16, 16, 16, __half, wmma::col_major> b_h, b_l;
                wmma::load_matrix_sync(b_h, Bh + (col0 + 16 * j) * 72 + kk, 72);
                wmma::load_matrix_sync(b_l, Bl + (col0 + 16 * j) * 72 + kk, 72);
                #pragma unroll
                for (int i = 0; i < 2; i++) {
                    wmma::mma_sync(am[i][j], a_h[i], b_h, am[i][j]);
                    wmma::mma_sync(ac[i][j], a_l[i], b_h, ac[i][j]);
                    wmma::mma_sync(ac[i][j], a_h[i], b_l, ac[i][j]);
                }
            }
        }
    }
    // epilogue: combine main + corr/2048, store to global
    float* outp = g_xproj + (size_t)dir * T_ * B_ * G_;
    #pragma unroll
    for (int i = 0; i < 2; i++)
        #pragma unroll
        for (int j = 0; j < 2; j++) {
            #pragma unroll
            for (int e = 0; e < am[i][j].num_elements; e++)
                am[i][j].x[e] += ac[i][j].x[e] * LO_INV;
            wmma::store_matrix_sync(outp + (m0 + row0 + 16 * i) * G_ + n0 + col0 + 16 * j,
                                    am[i][j], G_, wmma::mem_row_major);
        }
}

// ---------------- scan: persistent; W in register fragments; h read split from global ----
// 64 CTAs/dir, HS=8 gate cols per CTA (tile M=64 batch x N=32 gates x K=512).
// Warp w owns K-slice [64w, 64w+64).
#define NCPD 64
#define HS 8

__global__ void __launch_bounds__(256, 1) scan_kernel(
    const float* __restrict__ c0,
    const float* __restrict__ Whf, const float* __restrict__ Whb,
    const float* __restrict__ bf,  const float* __restrict__ bb,
    float* __restrict__ out)
{
    extern __shared__ __align__(16) char smraw[];
    float* red  = (float*)smraw;            // [8][64][36] warp partials (also aliases W staging)
    float* cS   = red + 8 * 64 * 36;        // [64][8]
    float* bias_s = cS + 64 * 8;            // [32]

    const int cta = blockIdx.x;
    const int dir = cta / NCPD;
    const int j   = cta % NCPD;
    const float* Wh   = dir ? Whb : Whf;
    const float* bias = dir ? bb : bf;
    const float* xp = g_xproj + (size_t)dir * T_ * B_ * G_;
    const int tid = threadIdx.x;
    const int w   = tid >> 5;

    // ---- prologue: stage split W slice in SMEM (aliasing red), build register frags ----
    {
        __half* Wsh = (__half*)red;          // [32][520]
        __half* Wsl = Wsh + 32 * 520;
        for (int idx = tid; idx < 32 * 512; idx += 256) {
            int c = idx >> 9, k = idx & 511;
            int wrow = (c >> 3) * H_ + j * HS + (c & 7);
            __half hi, lo;
            split_h16(Wh[(size_t)wrow * H_ + k], hi, lo);
            Wsh[c * 520 + k] = hi;
            Wsl[c * 520 + k] = lo;
        }
        if (tid < 32)
            bias_s[tid] = bias[(tid >> 3) * H_ + j * HS + (tid & 7)];
        #pragma unroll
        for (int idx = tid; idx < 64 * HS; idx += 256)
            cS[idx] = c0[((size_t)dir * B_ + (idx >> 3)) * H_ + j * HS + (idx & 7)];
        __syncthreads();

        // handled below (frags declared outside this scope)
    }

    wmma::fragment<wmma::matrix_b, 16, 16, 16, __half, wmma::col_major> bW_h[2][4], bW_l[2][4];
    {
        const __half* Wsh = (const __half*)red;
        const __half* Wsl = Wsh + 32 * 520;
        #pragma unroll
        for (int j2 = 0; j2 < 2; j2++)
            #pragma unroll
            for (int t4 = 0; t4 < 4; t4++) {
                wmma::load_matrix_sync(bW_h[j2][t4], Wsh + (j2 * 16) * 520 + w * 64 + t4 * 16, 520);
                wmma::load_matrix_sync(bW_l[j2][t4], Wsl + (j2 * 16) * 520 + w * 64 + t4 * 16, 520);
            }
    }
    __syncthreads();   // done reading W staging; red region now free

    for (int s = 0; s < T_; ++s) {
        const int cbuf = s & 1;
        const int t = dir ? (T_ - 1 - s) : s;
        const __half* hsrc_h = &g_hh[cbuf][dir][0][0];
        const __half* hsrc_l = &g_hl[cbuf][dir][0][0];
        const float* xpt = xp + (size_t)t * B_ * G_;

        // prefetch this thread's x_proj gate values (overlaps with MMA)
        float xg[2][4];
        #pragma unroll
        for (int q = 0; q < 2; q++) {
            int p = tid + q * 256;
            int b = p >> 3, hc = p & 7;
            #pragma unroll
            for (int g = 0; g < 4; g++)
                xg[q][g] = xpt[(size_t)b * G_ + g * H_ + j * HS + hc];
        }

        // MMA: warp w sums its K-slice; A fragments loaded split straight from global
        #pragma unroll
        for (int i = 0; i < 4; i++) {
            wmma::fragment<wmma::accumulator, 16, 16, 16, float> am[2], ac[2];
            wmma::fill_fragment(am[0], 0.f); wmma::fill_fragment(am[1], 0.f);
            wmma::fill_fragment(ac[0], 0.f); wmma::fill_fragment(ac[1], 0.f);
            #pragma unroll
            for (int t4 = 0; t4 < 4; t4++) {
                wmma::fragment<wmma::matrix_a, 16, 16, 16, __half, wmma::row_major> a_h, a_l;
                const int off = (i * 16) * H_ + w * 64 + t4 * 16;
                wmma::load_matrix_sync(a_h, hsrc_h + off, H_);
                wmma::load_matrix_sync(a_l, hsrc_l + off, H_);
                #pragma unroll
                for (int j2 = 0; j2 < 2; j2++) {
                    wmma::mma_sync(am[j2], a_h, bW_h[j2][t4], am[j2]);
                    wmma::mma_sync(ac[j2], a_l, bW_h[j2][t4], ac[j2]);
                    wmma::mma_sync(ac[j2], a_h, bW_l[j2][t4], ac[j2]);
                }
            }
            #pragma unroll
            for (int j2 = 0; j2 < 2; j2++) {
                #pragma unroll
                for (int e = 0; e < am[j2].num_elements; e++)
                    am[j2].x[e] += ac[j2].x[e] * LO_INV;
                wmma::store_matrix_sync(red + w * 2304 + (i * 16) * 36 + j2 * 16,
                                        am[j2], 36, wmma::mem_row_major);
            }
        }
        __syncthreads();

        // reduce 8 warp partials + LSTM cell; write split h
        __half* hdst_h = &g_hh[cbuf ^ 1][dir][0][0];
        __half* hdst_l = &g_hl[cbuf ^ 1][dir][0][0];
        #pragma unroll
        for (int q = 0; q < 2; q++) {
            int p = tid + q * 256;
            int b = p >> 3, hc = p & 7;
            float sum[4];
            #pragma unroll
            for (int g = 0; g < 4; g++) {
                float s0 = 0.f;
                #pragma unroll
                for (int ww = 0; ww < 8; ww++)
                    s0 += red[ww * 2304 + b * 36 + g * 8 + hc];
                sum[g] = s0 + xg[q][g] + bias_s[g * 8 + hc];
            }
            float ii = 1.f / (1.f + expf(-sum[0]));
            float ff = 1.f / (1.f + expf(-sum[1]));
            float g2 = tanhf(sum[2]);
            float oo = 1.f / (1.f + expf(-sum[3]));
            float cv = ff * cS[p] + ii * g2;
            cS[p] = cv;
            float hv = oo * tanhf(cv);
            __half hi, lo;
            split_h16(hv, hi, lo);
            hdst_h[b * H_ + j * HS + hc] = hi;
            hdst_l[b * H_ + j * HS + hc] = lo;
            out[((size_t)t * B_ + b) * (2 * H_) + dir * H_ + j * HS + hc] = hv;
        }
        __syncthreads();

        // grid barrier within this direction.
        // Writer: threadfence (release). Reader: spin then threadfence —
        // the gpu-scope fence emits CCTL.IVALL, invalidating L1 so the split-h
        // global loads above observe the other CTAs' writes.
        if (tid == 0) {
            __threadfence();
            atomicAdd(&g_bar[dir], 1u);
            unsigned target = (unsigned)(s + 1) * NCPD;
            volatile unsigned* p = &g_bar[dir];
            while (*p < target) __nanosleep(16);
            __threadfence();
        }
        __syncthreads();
    }
}

// ---------------- launch ----------------
extern "C" void kernel_launch(void* const* d_in, const int* in_sizes, int n_in,
                              void* d_out, int out_size)
{
    const float* x    = (const float*)d_in[0];
    const float* h0   = (const float*)d_in[1];
    const float* c0   = (const float*)d_in[2];
    const float* Wihf = (const float*)d_in[3];
    const float* Whhf = (const float*)d_in[4];
    const float* bf   = (const float*)d_in[5];
    const float* Wihb = (const float*)d_in[6];
    const float* Whhb = (const float*)d_in[7];
    const float* bb   = (const float*)d_in[8];
    float* out = (float*)d_out;

    // scan smem: (8*64*36 + 64*8 + 32) * 4 = 75904 B  (W staging aliases red)
    cudaFuncSetAttribute(scan_kernel, cudaFuncAttributeMaxDynamicSharedMemorySize, 75904);
    // xproj smem: (2*128*72 + 2*64*72) * 2 = 55296 B
    cudaFuncSetAttribute(xproj_kernel, cudaFuncAttributeMaxDynamicSharedMemorySize, 55296);

    dim3 gx(G_ / 64, (T_ * B_) / 128, 2);
    xproj_kernel<<<gx, 256, 55296>>>(x, Wihf, Wihb, h0);

    scan_kernel<<<128, 256, 75904>>>(c0, Whhf, Whhb, bf, bb, out);
}

// round 8
// speedup vs baseline: 3.8373x; 1.0697x over previous
#include <cuda_runtime.h>
#include <cuda_fp16.h>
#include <mma.h>

using namespace nvcuda;

#define T_ 512
#define B_ 64
#define I_ 512
#define H_ 512
#define G_ 2048   // 4*H

#define LO_SCALE   2048.f
#define LO_INV     4.8828125e-4f   // 1/2048

// ---------------- scratch (device globals: allowed) ----------------
__device__ float    g_xproj[2ull * T_ * B_ * G_];   // [dir][t][b][4H]
__device__ __half   g_hh[2][2][B_][H_];             // h split hi   [buf][dir][b][h]
__device__ __half   g_hl[2][2][B_][H_];             // h split lo * 2048
__device__ unsigned g_bar[2];

// Split fp32 -> fp16 hi + scaled fp16 lo. hi = RN(v); lo = RN((v - hi) * 2048).
__device__ __forceinline__ void split_h16(float v, __half& hi, __half& lo)
{
    hi = __float2half_rn(v);
    lo = __float2half_rn((v - __half2float(hi)) * LO_SCALE);
}

// ---------------- xproj: 3xFP16, split-at-fill, CTA 128x64; also does init ----------------
__global__ void __launch_bounds__(256, 2) xproj_kernel(
    const float* __restrict__ x,
    const float* __restrict__ Wf, const float* __restrict__ Wb,
    const float* __restrict__ h0)
{
    extern __shared__ __align__(16) char smraw[];
    __half* Ah = (__half*)smraw;          // [128][72]
    __half* Al = Ah + 128 * 72;
    __half* Bh = Al + 128 * 72;           // [64][72]
    __half* Bl = Bh + 64 * 72;

    const int tid = threadIdx.x;

    // ---- init fold: one CTA seeds split h state and resets the grid barrier ----
    if (blockIdx.x == 0 && blockIdx.y == 0 && blockIdx.z == 0) {
        if (tid < 2) g_bar[tid] = 0u;
        __half* hh = &g_hh[0][0][0][0];
        __half* hl = &g_hl[0][0][0][0];
        #pragma unroll 4
        for (int i = tid; i < 2 * B_ * H_; i += 256) {
            __half hi, lo;
            split_h16(h0[i], hi, lo);
            hh[i] = hi; hl[i] = lo;
        }
    }

    const int dir = blockIdx.z;
    const float* W = dir ? Wb : Wf;
    const size_t m0 = (size_t)blockIdx.y * 128;
    const int    n0 = blockIdx.x * 64;
    const int wid = tid >> 5;
    const int row0 = (wid & 3) * 32;   // warp grid 4(M) x 2(N), warp tile 32x32
    const int col0 = (wid >> 2) * 32;

    wmma::fragment<wmma::accumulator, 16, 16, 16, float> am[2][2], ac[2][2];
    #pragma unroll
    for (int i = 0; i < 2; i++)
        #pragma unroll
        for (int j = 0; j < 2; j++) { wmma::fill_fragment(am[i][j], 0.f); wmma::fill_fragment(ac[i][j], 0.f); }

    for (int k0 = 0; k0 < I_; k0 += 64) {
        __syncthreads();
        #pragma unroll
        for (int it = 0; it < 8; it++) {
            int f = tid + it * 256;          // 2048 float4: 128 rows x 16
            int r = f >> 4, c4 = f & 15;
            float4 v = *(const float4*)&x[(m0 + r) * I_ + k0 + c4 * 4];
            __half hx, lx, hy, ly, hz, lz, hw, lw;
            split_h16(v.x, hx, lx); split_h16(v.y, hy, ly);
            split_h16(v.z, hz, lz); split_h16(v.w, hw, lw);
            *(__half2*)&Ah[r * 72 + c4 * 4]     = __halves2half2(hx, hy);
            *(__half2*)&Ah[r * 72 + c4 * 4 + 2] = __halves2half2(hz, hw);
            *(__half2*)&Al[r * 72 + c4 * 4]     = __halves2half2(lx, ly);
            *(__half2*)&Al[r * 72 + c4 * 4 + 2] = __halves2half2(lz, lw);
        }
        #pragma unroll
        for (int it = 0; it < 4; it++) {
            int f = tid + it * 256;          // 1024 float4: 64 rows x 16
            int r = f >> 4, c4 = f & 15;
            float4 v = *(const float4*)&W[(size_t)(n0 + r) * I_ + k0 + c4 * 4];
            __half hx, lx, hy, ly, hz, lz, hw, lw;
            split_h16(v.x, hx, lx); split_h16(v.y, hy, ly);
            split_h16(v.z, hz, lz); split_h16(v.w, hw, lw);
            *(__half2*)&Bh[r * 72 + c4 * 4]     = __halves2half2(hx, hy);
            *(__half2*)&Bh[r * 72 + c4 * 4 + 2] = __halves2half2(hz, hw);
            *(__half2*)&Bl[r * 72 + c4 * 4]     = __halves2half2(lx, ly);
            *(__half2*)&Bl[r * 72 + c4 * 4 + 2] = __halves2half2(lz, lw);
        }
        __syncthreads();
        #pragma unroll
        for (int kk = 0; kk < 64; kk += 16) {
            wmma::fragment<wmma::matrix_a, 16, 16, 16, __half, wmma::row_major> a_h[2], a_l[2];
            #pragma unroll
            for (int i = 0; i < 2; i++) {
                wmma::load_matrix_sync(a_h[i], Ah + (row0 + 16 * i) * 72 + kk, 72);
                wmma::load_matrix_sync(a_l[i], Al + (row0 + 16 * i) * 72 + kk, 72);
            }
            #pragma unroll
            for (int j = 0; j < 2; j++) {
                wmma::fragment<wmma::matrix_b, 16, 16, 16, __half, wmma::col_major> b_h, b_l;
                wmma::load_matrix_sync(b_h, Bh + (col0 + 16 * j) * 72 + kk, 72);
                wmma::load_matrix_sync(b_l, Bl + (col0 + 16 * j) * 72 + kk, 72);
                #pragma unroll
                for (int i = 0; i < 2; i++) {
                    wmma::mma_sync(am[i][j], a_h[i], b_h, am[i][j]);
                    wmma::mma_sync(ac[i][j], a_l[i], b_h, ac[i][j]);
                    wmma::mma_sync(ac[i][j], a_h[i], b_l, ac[i][j]);
                }
            }
        }
    }
    float* outp = g_xproj + (size_t)dir * T_ * B_ * G_;
    #pragma unroll
    for (int i = 0; i < 2; i++)
        #pragma unroll
        for (int j = 0; j < 2; j++) {
            #pragma unroll
            for (int e = 0; e < am[i][j].num_elements; e++)
                am[i][j].x[e] += ac[i][j].x[e] * LO_INV;
            wmma::store_matrix_sync(outp + (m0 + row0 + 16 * i) * G_ + n0 + col0 + 16 * j,
                                    am[i][j], G_, wmma::mem_row_major);
        }
}

// ---------------- scan: persistent; W in register fragments; h staged in SMEM (LDSM) ----
// 64 CTAs/dir, HS=8 gate cols per CTA (tile M=64 batch x N=32 gates x K=512).
// Warp w owns K-slice [64w, 64w+64).
// SMEM h stride 520 halves = 1040B == 16 (mod 128): conflict-free ldmatrix & float4 STS.
#define NCPD 64
#define HS 8
#define HSTR 520

__global__ void __launch_bounds__(256, 1) scan_kernel(
    const float* __restrict__ c0,
    const float* __restrict__ Whf, const float* __restrict__ Whb,
    const float* __restrict__ bf,  const float* __restrict__ bb,
    float* __restrict__ out)
{
    extern __shared__ __align__(16) char smraw[];
    __half* hSh = (__half*)smraw;            // [64][520]
    __half* hSl = hSh + 64 * HSTR;           // [64][520]
    float*  red = (float*)(hSl + 64 * HSTR); // [8][64][36] warp partials
    float*  cS  = red + 8 * 64 * 36;         // [64][8]
    float*  bias_s = cS + 64 * 8;            // [32]

    const int cta = blockIdx.x;
    const int dir = cta / NCPD;
    const int j   = cta % NCPD;
    const float* Wh   = dir ? Whb : Whf;
    const float* bias = dir ? bb : bf;
    const float* xp = g_xproj + (size_t)dir * T_ * B_ * G_;
    const int tid = threadIdx.x;
    const int w   = tid >> 5;

    // ---- prologue: stage split W slice (aliases the h staging region), build register frags ----
    {
        __half* Wsh = hSh;                   // [32][520]
        __half* Wsl = Wsh + 32 * HSTR;
        for (int idx = tid; idx < 32 * 512; idx += 256) {
            int c = idx >> 9, k = idx & 511;
            int wrow = (c >> 3) * H_ + j * HS + (c & 7);
            __half hi, lo;
            split_h16(Wh[(size_t)wrow * H_ + k], hi, lo);
            Wsh[c * HSTR + k] = hi;
            Wsl[c * HSTR + k] = lo;
        }
        if (tid < 32)
            bias_s[tid] = bias[(tid >> 3) * H_ + j * HS + (tid & 7)];
        #pragma unroll
        for (int idx = tid; idx < 64 * HS; idx += 256)
            cS[idx] = c0[((size_t)dir * B_ + (idx >> 3)) * H_ + j * HS + (idx & 7)];
        __syncthreads();
    }

    wmma::fragment<wmma::matrix_b, 16, 16, 16, __half, wmma::col_major> bW_h[2][4], bW_l[2][4];
    {
        const __half* Wsh = hSh;
        const __half* Wsl = Wsh + 32 * HSTR;
        #pragma unroll
        for (int j2 = 0; j2 < 2; j2++)
            #pragma unroll
            for (int t4 = 0; t4 < 4; t4++) {
                wmma::load_matrix_sync(bW_h[j2][t4], Wsh + (j2 * 16) * HSTR + w * 64 + t4 * 16, HSTR);
                wmma::load_matrix_sync(bW_l[j2][t4], Wsl + (j2 * 16) * HSTR + w * 64 + t4 * 16, HSTR);
            }
    }
    __syncthreads();   // done reading W staging; h staging region now free

    for (int s = 0; s < T_; ++s) {
        const int cbuf = s & 1;
        const int t = dir ? (T_ - 1 - s) : s;
        const __half* hsrc_h = &g_hh[cbuf][dir][0][0];
        const __half* hsrc_l = &g_hl[cbuf][dir][0][0];
        const float* xpt = xp + (size_t)t * B_ * G_;

        // prefetch this thread's x_proj gate values (overlaps with staging latency)
        float xg[2][4];
        #pragma unroll
        for (int q = 0; q < 2; q++) {
            int p = tid + q * 256;
            int b = p >> 3, hc = p & 7;
            #pragma unroll
            for (int g = 0; g < 4; g++)
                xg[q][g] = xpt[(size_t)b * G_ + g * H_ + j * HS + hc];
        }

        // stage split h: coalesced float4 global->SMEM.
        // 4096 float4 slots = 64 rows x 64 float4-chunks (512 halves) per buffer.
        #pragma unroll
        for (int q = 0; q < 16; q++) {
            int slot = tid + q * 256;
            int r = slot >> 6, c8 = (slot & 63) * 8;   // FIXED: was >>5 / &31 (OOB + half-row gap)
            *(float4*)&hSh[r * HSTR + c8] = *(const float4*)&hsrc_h[r * H_ + c8];
            *(float4*)&hSl[r * HSTR + c8] = *(const float4*)&hsrc_l[r * H_ + c8];
        }
        __syncthreads();

        // MMA: warp w sums its K-slice; A fragments via LDSM from SMEM
        #pragma unroll
        for (int i = 0; i < 4; i++) {
            wmma::fragment<wmma::accumulator, 16, 16, 16, float> am[2], ac[2];
            wmma::fill_fragment(am[0], 0.f); wmma::fill_fragment(am[1], 0.f);
            wmma::fill_fragment(ac[0], 0.f); wmma::fill_fragment(ac[1], 0.f);
            #pragma unroll
            for (int t4 = 0; t4 < 4; t4++) {
                wmma::fragment<wmma::matrix_a, 16, 16, 16, __half, wmma::row_major> a_h, a_l;
                const int off = (i * 16) * HSTR + w * 64 + t4 * 16;
                wmma::load_matrix_sync(a_h, hSh + off, HSTR);
                wmma::load_matrix_sync(a_l, hSl + off, HSTR);
                #pragma unroll
                for (int j2 = 0; j2 < 2; j2++) {
                    wmma::mma_sync(am[j2], a_h, bW_h[j2][t4], am[j2]);
                    wmma::mma_sync(ac[j2], a_l, bW_h[j2][t4], ac[j2]);
                    wmma::mma_sync(ac[j2], a_h, bW_l[j2][t4], ac[j2]);
                }
            }
            #pragma unroll
            for (int j2 = 0; j2 < 2; j2++) {
                #pragma unroll
                for (int e = 0; e < am[j2].num_elements; e++)
                    am[j2].x[e] += ac[j2].x[e] * LO_INV;
                wmma::store_matrix_sync(red + w * 2304 + (i * 16) * 36 + j2 * 16,
                                        am[j2], 36, wmma::mem_row_major);
            }
        }
        __syncthreads();

        // reduce 8 warp partials + LSTM cell; write split h
        __half* hdst_h = &g_hh[cbuf ^ 1][dir][0][0];
        __half* hdst_l = &g_hl[cbuf ^ 1][dir][0][0];
        #pragma unroll
        for (int q = 0; q < 2; q++) {
            int p = tid + q * 256;
            int b = p >> 3, hc = p & 7;
            float sum[4];
            #pragma unroll
            for (int g = 0; g < 4; g++) {
                float s0 = 0.f;
                #pragma unroll
                for (int ww = 0; ww < 8; ww++)
                    s0 += red[ww * 2304 + b * 36 + g * 8 + hc];
                sum[g] = s0 + xg[q][g] + bias_s[g * 8 + hc];
            }
            float ii = 1.f / (1.f + expf(-sum[0]));
            float ff = 1.f / (1.f + expf(-sum[1]));
            float g2 = tanhf(sum[2]);
            float oo = 1.f / (1.f + expf(-sum[3]));
            float cv = ff * cS[p] + ii * g2;
            cS[p] = cv;
            float hv = oo * tanhf(cv);
            __half hi, lo;
            split_h16(hv, hi, lo);
            hdst_h[b * H_ + j * HS + hc] = hi;
            hdst_l[b * H_ + j * HS + hc] = lo;
            out[((size_t)t * B_ + b) * (2 * H_) + dir * H_ + j * HS + hc] = hv;
        }
        __syncthreads();

        // grid barrier within this direction (release-acquire; reader fence
        // emits CCTL.IVALL so next step's h loads see peer CTAs' writes)
        if (tid == 0) {
            __threadfence();
            atomicAdd(&g_bar[dir], 1u);
            unsigned target = (unsigned)(s + 1) * NCPD;
            volatile unsigned* p = &g_bar[dir];
            while (*p < target) __nanosleep(16);
            __threadfence();
        }
        __syncthreads();
    }
}

// ---------------- launch ----------------
extern "C" void kernel_launch(void* const* d_in, const int* in_sizes, int n_in,
                              void* d_out, int out_size)
{
    const float* x    = (const float*)d_in[0];
    const float* h0   = (const float*)d_in[1];
    const float* c0   = (const float*)d_in[2];
    const float* Wihf = (const float*)d_in[3];
    const float* Whhf = (const float*)d_in[4];
    const float* bf   = (const float*)d_in[5];
    const float* Wihb = (const float*)d_in[6];
    const float* Whhb = (const float*)d_in[7];
    const float* bb   = (const float*)d_in[8];
    float* out = (float*)d_out;

    // scan smem: 2*64*520*2 + (8*64*36 + 64*8 + 32)*4 = 209024 B
    cudaFuncSetAttribute(scan_kernel, cudaFuncAttributeMaxDynamicSharedMemorySize, 209024);
    // xproj smem: (2*128*72 + 2*64*72) * 2 = 55296 B
    cudaFuncSetAttribute(xproj_kernel, cudaFuncAttributeMaxDynamicSharedMemorySize, 55296);

    dim3 gx(G_ / 64, (T_ * B_) / 128, 2);
    xproj_kernel<<<gx, 256, 55296>>>(x, Wihf, Wihb, h0);

    scan_kernel<<<128, 256, 209024>>>(c0, Whhf, Whhb, bf, bb, out);
}

// round 9
// speedup vs baseline: 4.3535x; 1.1345x over previous
#include <cuda_runtime.h>
#include <cuda_fp16.h>
#include <mma.h>

using namespace nvcuda;

#define T_ 512
#define B_ 64
#define I_ 512
#define H_ 512
#define G_ 2048   // 4*H

#define LO_SCALE   2048.f
#define LO_INV     4.8828125e-4f   // 1/2048

// ---------------- scratch (device globals: allowed) ----------------
__device__ float    g_xproj[2ull * T_ * B_ * G_];   // [dir][t][b][4H]
__device__ __half   g_hh[2][2][B_][H_];             // h split hi   [buf][dir][b][h]
__device__ __half   g_hl[2][2][B_][H_];             // h split lo * 2048
__device__ unsigned g_bar[2];

// Split fp32 -> fp16 hi + scaled fp16 lo.
__device__ __forceinline__ void split_h16(float v, __half& hi, __half& lo)
{
    hi = __float2half_rn(v);
    lo = __float2half_rn((v - __half2float(hi)) * LO_SCALE);
}

__device__ __forceinline__ void stcg_half(__half* p, __half v)
{
    unsigned short u = __half_as_ushort(v);
    asm volatile("st.global.cg.u16 [%0], %1;" :: "l"(p), "h"(u) : "memory");
}

// fast-but-accurate gates: __expf max err ~few ulp, __fdividef ~2 ulp
__device__ __forceinline__ float fsig(float x)  { return __fdividef(1.f, 1.f + __expf(-x)); }
__device__ __forceinline__ float ftanh(float x) { return __fdividef(2.f, 1.f + __expf(-2.f * x)) - 1.f; }

// ---------------- xproj: 3xFP16, split-at-fill, CTA 128x64; also does init ----------------
__global__ void __launch_bounds__(256, 2) xproj_kernel(
    const float* __restrict__ x,
    const float* __restrict__ Wf, const float* __restrict__ Wb,
    const float* __restrict__ h0)
{
    extern __shared__ __align__(16) char smraw[];
    __half* Ah = (__half*)smraw;          // [128][72]
    __half* Al = Ah + 128 * 72;
    __half* Bh = Al + 128 * 72;           // [64][72]
    __half* Bl = Bh + 64 * 72;

    const int tid = threadIdx.x;

    if (blockIdx.x == 0 && blockIdx.y == 0 && blockIdx.z == 0) {
        if (tid < 2) g_bar[tid] = 0u;
        __half* hh = &g_hh[0][0][0][0];
        __half* hl = &g_hl[0][0][0][0];
        #pragma unroll 4
        for (int i = tid; i < 2 * B_ * H_; i += 256) {
            __half hi, lo;
            split_h16(h0[i], hi, lo);
            hh[i] = hi; hl[i] = lo;
        }
    }

    const int dir = blockIdx.z;
    const float* W = dir ? Wb : Wf;
    const size_t m0 = (size_t)blockIdx.y * 128;
    const int    n0 = blockIdx.x * 64;
    const int wid = tid >> 5;
    const int row0 = (wid & 3) * 32;
    const int col0 = (wid >> 2) * 32;

    wmma::fragment<wmma::accumulator, 16, 16, 16, float> am[2][2], ac[2][2];
    #pragma unroll
    for (int i = 0; i < 2; i++)
        #pragma unroll
        for (int j = 0; j < 2; j++) { wmma::fill_fragment(am[i][j], 0.f); wmma::fill_fragment(ac[i][j], 0.f); }

    for (int k0 = 0; k0 < I_; k0 += 64) {
        __syncthreads();
        #pragma unroll
        for (int it = 0; it < 8; it++) {
            int f = tid + it * 256;
            int r = f >> 4, c4 = f & 15;
            float4 v = *(const float4*)&x[(m0 + r) * I_ + k0 + c4 * 4];
            __half hx, lx, hy, ly, hz, lz, hw, lw;
            split_h16(v.x, hx, lx); split_h16(v.y, hy, ly);
            split_h16(v.z, hz, lz); split_h16(v.w, hw, lw);
            *(__half2*)&Ah[r * 72 + c4 * 4]     = __halves2half2(hx, hy);
            *(__half2*)&Ah[r * 72 + c4 * 4 + 2] = __halves2half2(hz, hw);
            *(__half2*)&Al[r * 72 + c4 * 4]     = __halves2half2(lx, ly);
            *(__half2*)&Al[r * 72 + c4 * 4 + 2] = __halves2half2(lz, lw);
        }
        #pragma unroll
        for (int it = 0; it < 4; it++) {
            int f = tid + it * 256;
            int r = f >> 4, c4 = f & 15;
            float4 v = *(const float4*)&W[(size_t)(n0 + r) * I_ + k0 + c4 * 4];
            __half hx, lx, hy, ly, hz, lz, hw, lw;
            split_h16(v.x, hx, lx); split_h16(v.y, hy, ly);
            split_h16(v.z, hz, lz); split_h16(v.w, hw, lw);
            *(__half2*)&Bh[r * 72 + c4 * 4]     = __halves2half2(hx, hy);
            *(__half2*)&Bh[r * 72 + c4 * 4 + 2] = __halves2half2(hz, hw);
            *(__half2*)&Bl[r * 72 + c4 * 4]     = __halves2half2(lx, ly);
            *(__half2*)&Bl[r * 72 + c4 * 4 + 2] = __halves2half2(lz, lw);
        }
        __syncthreads();
        #pragma unroll
        for (int kk = 0; kk < 64; kk += 16) {
            wmma::fragment<wmma::matrix_a, 16, 16, 16, __half, wmma::row_major> a_h[2], a_l[2];
            #pragma unroll
            for (int i = 0; i < 2; i++) {
                wmma::load_matrix_sync(a_h[i], Ah + (row0 + 16 * i) * 72 + kk, 72);
                wmma::load_matrix_sync(a_l[i], Al + (row0 + 16 * i) * 72 + kk, 72);
            }
            #pragma unroll
            for (int j = 0; j < 2; j++) {
                wmma::fragment<wmma::matrix_b, 16, 16, 16, __half, wmma::col_major> b_h, b_l;
                wmma::load_matrix_sync(b_h, Bh + (col0 + 16 * j) * 72 + kk, 72);
                wmma::load_matrix_sync(b_l, Bl + (col0 + 16 * j) * 72 + kk, 72);
                #pragma unroll
                for (int i = 0; i < 2; i++) {
                    wmma::mma_sync(am[i][j], a_h[i], b_h, am[i][j]);
                    wmma::mma_sync(ac[i][j], a_l[i], b_h, ac[i][j]);
                    wmma::mma_sync(ac[i][j], a_h[i], b_l, ac[i][j]);
                }
            }
        }
    }
    float* outp = g_xproj + (size_t)dir * T_ * B_ * G_;
    #pragma unroll
    for (int i = 0; i < 2; i++)
        #pragma unroll
        for (int j = 0; j < 2; j++) {
            #pragma unroll
            for (int e = 0; e < am[i][j].num_elements; e++)
                am[i][j].x[e] += ac[i][j].x[e] * LO_INV;
            wmma::store_matrix_sync(outp + (m0 + row0 + 16 * i) * G_ + n0 + col0 + 16 * j,
                                    am[i][j], G_, wmma::mem_row_major);
        }
}

// ---------------- scan: persistent; per-warp K-slice fill; .cg h exchange ----------------
#define NCPD 64
#define HS 8
#define HSTR 520   // 1040B stride == 16 mod 128: conflict-free LDSM + float4 STS

__global__ void __launch_bounds__(256, 1) scan_kernel(
    const float* __restrict__ c0,
    const float* __restrict__ Whf, const float* __restrict__ Whb,
    const float* __restrict__ bf,  const float* __restrict__ bb,
    float* __restrict__ out)
{
    extern __shared__ __align__(16) char smraw[];
    __half* hSh = (__half*)smraw;            // [64][520]
    __half* hSl = hSh + 64 * HSTR;           // [64][520]
    float*  red = (float*)(hSl + 64 * HSTR); // [8][64][36] warp partials
    float*  cS  = red + 8 * 64 * 36;         // [64][8]
    float*  bias_s = cS + 64 * 8;            // [32]

    const int cta = blockIdx.x;
    const int dir = cta / NCPD;
    const int j   = cta % NCPD;
    const float* Wh   = dir ? Whb : Whf;
    const float* bias = dir ? bb : bf;
    const float* xp = g_xproj + (size_t)dir * T_ * B_ * G_;
    const int tid  = threadIdx.x;
    const int w    = tid >> 5;
    const int lane = tid & 31;

    // ---- prologue: stage split W slice (aliases h staging), build register frags ----
    {
        __half* Wsh = hSh;                   // [32][520]
        __half* Wsl = Wsh + 32 * HSTR;
        for (int idx = tid; idx < 32 * 512; idx += 256) {
            int c = idx >> 9, k = idx & 511;
            int wrow = (c >> 3) * H_ + j * HS + (c & 7);
            __half hi, lo;
            split_h16(Wh[(size_t)wrow * H_ + k], hi, lo);
            Wsh[c * HSTR + k] = hi;
            Wsl[c * HSTR + k] = lo;
        }
        if (tid < 32)
            bias_s[tid] = bias[(tid >> 3) * H_ + j * HS + (tid & 7)];
        #pragma unroll
        for (int idx = tid; idx < 64 * HS; idx += 256)
            cS[idx] = c0[((size_t)dir * B_ + (idx >> 3)) * H_ + j * HS + (idx & 7)];
        __syncthreads();
    }

    wmma::fragment<wmma::matrix_b, 16, 16, 16, __half, wmma::col_major> bW_h[2][4], bW_l[2][4];
    {
        const __half* Wsh = hSh;
        const __half* Wsl = Wsh + 32 * HSTR;
        #pragma unroll
        for (int j2 = 0; j2 < 2; j2++)
            #pragma unroll
            for (int t4 = 0; t4 < 4; t4++) {
                wmma::load_matrix_sync(bW_h[j2][t4], Wsh + (j2 * 16) * HSTR + w * 64 + t4 * 16, HSTR);
                wmma::load_matrix_sync(bW_l[j2][t4], Wsl + (j2 * 16) * HSTR + w * 64 + t4 * 16, HSTR);
            }
    }
    __syncthreads();   // W staging done; h staging region free

    for (int s = 0; s < T_; ++s) {
        const int cbuf = s & 1;
        const int t = dir ? (T_ - 1 - s) : s;
        const __half* hsrc_h = &g_hh[cbuf][dir][0][0];
        const __half* hsrc_l = &g_hl[cbuf][dir][0][0];
        const float* xpt = xp + (size_t)t * B_ * G_;

        // xg prefetch (independent; overlaps everything until the cell phase)
        float xg[2][4];
        #pragma unroll
        for (int q = 0; q < 2; q++) {
            int p = tid + q * 256;
            int b = p >> 3, hc = p & 7;
            #pragma unroll
            for (int g = 0; g < 4; g++)
                xg[q][g] = xpt[(size_t)b * G_ + g * H_ + j * HS + hc];
        }

        // per-warp fill: warp w stages ONLY its K-slice [64w,64w+64) (hi+lo), .cg loads.
        // lane mapping: 512 float4 per buf-slice; slot = lane + 32q; r = slot>>3, chunk = slot&7.
        #pragma unroll
        for (int q = 0; q < 16; q++) {
            int slot = lane + q * 32;
            int r = slot >> 3, c8 = (slot & 7) * 8;
            const int go = r * H_ + w * 64 + c8;
            const int so = r * HSTR + w * 64 + c8;
            *(float4*)&hSh[so] = __ldcg((const float4*)&hsrc_h[go]);
            *(float4*)&hSl[so] = __ldcg((const float4*)&hsrc_l[go]);
        }
        __syncwarp();

        // MMA on own slice (LDSM); store partials to red[w]
        #pragma unroll
        for (int i = 0; i < 4; i++) {
            wmma::fragment<wmma::accumulator, 16, 16, 16, float> am[2], ac[2];
            wmma::fill_fragment(am[0], 0.f); wmma::fill_fragment(am[1], 0.f);
            wmma::fill_fragment(ac[0], 0.f); wmma::fill_fragment(ac[1], 0.f);
            #pragma unroll
            for (int t4 = 0; t4 < 4; t4++) {
                wmma::fragment<wmma::matrix_a, 16, 16, 16, __half, wmma::row_major> a_h, a_l;
                const int off = (i * 16) * HSTR + w * 64 + t4 * 16;
                wmma::load_matrix_sync(a_h, hSh + off, HSTR);
                wmma::load_matrix_sync(a_l, hSl + off, HSTR);
                #pragma unroll
                for (int j2 = 0; j2 < 2; j2++) {
                    wmma::mma_sync(am[j2], a_h, bW_h[j2][t4], am[j2]);
                    wmma::mma_sync(ac[j2], a_l, bW_h[j2][t4], ac[j2]);
                    wmma::mma_sync(ac[j2], a_h, bW_l[j2][t4], ac[j2]);
                }
            }
            #pragma unroll
            for (int j2 = 0; j2 < 2; j2++) {
                #pragma unroll
                for (int e = 0; e < am[j2].num_elements; e++)
                    am[j2].x[e] += ac[j2].x[e] * LO_INV;
                wmma::store_matrix_sync(red + w * 2304 + (i * 16) * 36 + j2 * 16,
                                        am[j2], 36, wmma::mem_row_major);
            }
        }
        __syncthreads();   // all partials visible

        // reduce 8 warp partials + LSTM cell; write split h via .cg (L2-coherent)
        __half* hdst_h = &g_hh[cbuf ^ 1][dir][0][0];
        __half* hdst_l = &g_hl[cbuf ^ 1][dir][0][0];
        #pragma unroll
        for (int q = 0; q < 2; q++) {
            int p = tid + q * 256;
            int b = p >> 3, hc = p & 7;
            float sum[4];
            #pragma unroll
            for (int g = 0; g < 4; g++) {
                float s0 = 0.f;
                #pragma unroll
                for (int ww = 0; ww < 8; ww++)
                    s0 += red[ww * 2304 + b * 36 + g * 8 + hc];
                sum[g] = s0 + xg[q][g] + bias_s[g * 8 + hc];
            }
            float ii = fsig(sum[0]);
            float ff = fsig(sum[1]);
            float g2 = ftanh(sum[2]);
            float oo = fsig(sum[3]);
            float cv = ff * cS[p] + ii * g2;
            cS[p] = cv;
            float hv = oo * ftanh(cv);
            __half hi, lo;
            split_h16(hv, hi, lo);
            stcg_half(&hdst_h[b * H_ + j * HS + hc], hi);
            stcg_half(&hdst_l[b * H_ + j * HS + hc], lo);
            out[((size_t)t * B_ + b) * (2 * H_) + dir * H_ + j * HS + hc] = hv;
        }
        __syncthreads();   // all h stores issued before tid0 releases

        // grid barrier within this direction. Writer: fence (release) + atomic.
        // Reader: tight spin; NO acquire fence needed — h exchange is .cg (L2 is
        // the point of coherence), so no stale-L1 hazard and no CCTL.IVALL cost.
        if (tid == 0) {
            __threadfence();
            atomicAdd(&g_bar[dir], 1u);
            unsigned target = (unsigned)(s + 1) * NCPD;
            volatile unsigned* bp = &g_bar[dir];
            while (*bp < target) { }
        }
        __syncthreads();
    }
}

// ---------------- launch ----------------
extern "C" void kernel_launch(void* const* d_in, const int* in_sizes, int n_in,
                              void* d_out, int out_size)
{
    const float* x    = (const float*)d_in[0];
    const float* h0   = (const float*)d_in[1];
    const float* c0   = (const float*)d_in[2];
    const float* Wihf = (const float*)d_in[3];
    const float* Whhf = (const float*)d_in[4];
    const float* bf   = (const float*)d_in[5];
    const float* Wihb = (const float*)d_in[6];
    const float* Whhb = (const float*)d_in[7];
    const float* bb   = (const float*)d_in[8];
    float* out = (float*)d_out;

    // scan smem: 2*64*520*2 + (8*64*36 + 64*8 + 32)*4 = 209024 B
    cudaFuncSetAttribute(scan_kernel, cudaFuncAttributeMaxDynamicSharedMemorySize, 209024);
    // xproj smem: (2*128*72 + 2*64*72) * 2 = 55296 B
    cudaFuncSetAttribute(xproj_kernel, cudaFuncAttributeMaxDynamicSharedMemorySize, 55296);

    dim3 gx(G_ / 64, (T_ * B_) / 128, 2);
    xproj_kernel<<<gx, 256, 55296>>>(x, Wihf, Wihb, h0);

    scan_kernel<<<128, 256, 209024>>>(c0, Whhf, Whhb, bf, bb, out);
}

// round 11
// speedup vs baseline: 4.6419x; 1.0662x over previous
#include <cuda_runtime.h>
#include <cuda_fp16.h>
#include <mma.h>

using namespace nvcuda;

#define T_ 512
#define B_ 64
#define I_ 512
#define H_ 512
#define G_ 2048   // 4*H

#define LO_SCALE   2048.f
#define LO_INV     4.8828125e-4f   // 1/2048

// ---------------- scratch (device globals: allowed) ----------------
__device__ float    g_xproj[2ull * T_ * B_ * G_];   // [dir][t][b][4H]
__device__ __half   g_hh[2][2][B_][H_];             // h split hi   [buf][dir][b][h]
__device__ __half   g_hl[2][2][B_][H_];             // h split lo * 2048
__device__ unsigned g_bar[2][32];                   // per-dir counters, 128B apart

__device__ __forceinline__ void split_h16(float v, __half& hi, __half& lo)
{
    hi = __float2half_rn(v);
    lo = __float2half_rn((v - __half2float(hi)) * LO_SCALE);
}

__device__ __forceinline__ unsigned h2_bits(__half a, __half b)
{
    __half2 h2 = __halves2half2(a, b);
    return *reinterpret_cast<unsigned*>(&h2);
}

__device__ __forceinline__ void stcg_u32(void* p, unsigned v)
{
    asm volatile("st.global.cg.u32 [%0], %1;" :: "l"(p), "r"(v) : "memory");
}

__device__ __forceinline__ void cp_async_cg16(void* smem, const void* gmem)
{
    unsigned sa = (unsigned)__cvta_generic_to_shared(smem);
    asm volatile("cp.async.cg.shared.global [%0], [%1], 16;" :: "r"(sa), "l"(gmem) : "memory");
}
__device__ __forceinline__ void cp_async_commit_wait()
{
    asm volatile("cp.async.commit_group;\n\tcp.async.wait_group 0;" ::: "memory");
}

__device__ __forceinline__ float fsig(float x)  { return __fdividef(1.f, 1.f + __expf(-x)); }
__device__ __forceinline__ float ftanh(float x) { return __fdividef(2.f, 1.f + __expf(-2.f * x)) - 1.f; }

// ---------------- xproj: 3xFP16, split-at-fill, CTA 128x64; also does init ----------------
__global__ void __launch_bounds__(256, 2) xproj_kernel(
    const float* __restrict__ x,
    const float* __restrict__ Wf, const float* __restrict__ Wb,
    const float* __restrict__ h0)
{
    extern __shared__ __align__(16) char smraw[];
    __half* Ah = (__half*)smraw;          // [128][72]
    __half* Al = Ah + 128 * 72;
    __half* Bh = Al + 128 * 72;           // [64][72]
    __half* Bl = Bh + 64 * 72;

    const int tid = threadIdx.x;

    if (blockIdx.x == 0 && blockIdx.y == 0 && blockIdx.z == 0) {
        if (tid < 2) g_bar[tid][0] = 0u;
        __half* hh = &g_hh[0][0][0][0];
        __half* hl = &g_hl[0][0][0][0];
        #pragma unroll 4
        for (int i = tid; i < 2 * B_ * H_; i += 256) {
            __half hi, lo;
            split_h16(h0[i], hi, lo);
            hh[i] = hi; hl[i] = lo;
        }
    }

    const int dir = blockIdx.z;
    const float* W = dir ? Wb : Wf;
    const size_t m0 = (size_t)blockIdx.y * 128;
    const int    n0 = blockIdx.x * 64;
    const int wid = tid >> 5;
    const int row0 = (wid & 3) * 32;
    const int col0 = (wid >> 2) * 32;

    wmma::fragment<wmma::accumulator, 16, 16, 16, float> am[2][2], ac[2][2];
    #pragma unroll
    for (int i = 0; i < 2; i++)
        #pragma unroll
        for (int j = 0; j < 2; j++) { wmma::fill_fragment(am[i][j], 0.f); wmma::fill_fragment(ac[i][j], 0.f); }

    for (int k0 = 0; k0 < I_; k0 += 64) {
        __syncthreads();
        #pragma unroll
        for (int it = 0; it < 8; it++) {
            int f = tid + it * 256;
            int r = f >> 4, c4 = f & 15;
            float4 v = *(const float4*)&x[(m0 + r) * I_ + k0 + c4 * 4];
            __half hx, lx, hy, ly, hz, lz, hw, lw;
            split_h16(v.x, hx, lx); split_h16(v.y, hy, ly);
            split_h16(v.z, hz, lz); split_h16(v.w, hw, lw);
            *(__half2*)&Ah[r * 72 + c4 * 4]     = __halves2half2(hx, hy);
            *(__half2*)&Ah[r * 72 + c4 * 4 + 2] = __halves2half2(hz, hw);
            *(__half2*)&Al[r * 72 + c4 * 4]     = __halves2half2(lx, ly);
            *(__half2*)&Al[r * 72 + c4 * 4 + 2] = __halves2half2(lz, lw);
        }
        #pragma unroll
        for (int it = 0; it < 4; it++) {
            int f = tid + it * 256;
            int r = f >> 4, c4 = f & 15;
            float4 v = *(const float4*)&W[(size_t)(n0 + r) * I_ + k0 + c4 * 4];
            __half hx, lx, hy, ly, hz, lz, hw, lw;
            split_h16(v.x, hx, lx); split_h16(v.y, hy, ly);
            split_h16(v.z, hz, lz); split_h16(v.w, hw, lw);
            *(__half2*)&Bh[r * 72 + c4 * 4]     = __halves2half2(hx, hy);
            *(__half2*)&Bh[r * 72 + c4 * 4 + 2] = __halves2half2(hz, hw);
            *(__half2*)&Bl[r * 72 + c4 * 4]     = __halves2half2(lx, ly);
            *(__half2*)&Bl[r * 72 + c4 * 4 + 2] = __halves2half2(lz, lw);
        }
        __syncthreads();
        #pragma unroll
        for (int kk = 0; kk < 64; kk += 16) {
            wmma::fragment<wmma::matrix_a, 16, 16, 16, __half, wmma::row_major> a_h[2], a_l[2];
            #pragma unroll
            for (int i = 0; i < 2; i++) {
                wmma::load_matrix_sync(a_h[i], Ah + (row0 + 16 * i) * 72 + kk, 72);
                wmma::load_matrix_sync(a_l[i], Al + (row0 + 16 * i) * 72 + kk, 72);
            }
            #pragma unroll
            for (int j = 0; j < 2; j++) {
                wmma::fragment<wmma::matrix_b, 16, 16, 16, __half, wmma::col_major> b_h, b_l;
                wmma::load_matrix_sync(b_h, Bh + (col0 + 16 * j) * 72 + kk, 72);
                wmma::load_matrix_sync(b_l, Bl + (col0 + 16 * j) * 72 + kk, 72);
                #pragma unroll
                for (int i = 0; i < 2; i++) {
                    wmma::mma_sync(am[i][j], a_h[i], b_h, am[i][j]);
                    wmma::mma_sync(ac[i][j], a_l[i], b_h, ac[i][j]);
                    wmma::mma_sync(ac[i][j], a_h[i], b_l, ac[i][j]);
                }
            }
        }
    }
    float* outp = g_xproj + (size_t)dir * T_ * B_ * G_;
    #pragma unroll
    for (int i = 0; i < 2; i++)
        #pragma unroll
        for (int j = 0; j < 2; j++) {
            #pragma unroll
            for (int e = 0; e < am[i][j].num_elements; e++)
                am[i][j].x[e] += ac[i][j].x[e] * LO_INV;
            wmma::store_matrix_sync(outp + (m0 + row0 + 16 * i) * G_ + n0 + col0 + 16 * j,
                                    am[i][j], G_, wmma::mem_row_major);
        }
}

// ---------------- scan: persistent; cp.async fill; vectorized reduce ----------------
#define NCPD 64
#define HS 8
#define HSTR 520   // 1040B == 16 mod 128: conflict-free LDSM + 16B cp.async
#define RSTR 40    // red stride: granule stride 20 -> all 32 banks distinct for float2 reduce

__global__ void __launch_bounds__(256, 1) scan_kernel(
    const float* __restrict__ c0,
    const float* __restrict__ Whf, const float* __restrict__ Whb,
    const float* __restrict__ bf,  const float* __restrict__ bb,
    float* __restrict__ out)
{
    extern __shared__ __align__(16) char smraw[];
    __half* hSh = (__half*)smraw;            // [64][520]
    __half* hSl = hSh + 64 * HSTR;           // [64][520]
    float*  red = (float*)(hSl + 64 * HSTR); // [8][64][40] warp partials
    float*  cS  = red + 8 * 64 * RSTR;       // [64][8]
    float*  bias_s = cS + 64 * 8;            // [32]

    const int cta = blockIdx.x;
    const int dir = cta / NCPD;
    const int j   = cta % NCPD;
    const float* Wh   = dir ? Whb : Whf;
    const float* bias = dir ? bb : bf;
    const float* xp = g_xproj + (size_t)dir * T_ * B_ * G_;
    const int tid  = threadIdx.x;
    const int w    = tid >> 5;
    const int lane = tid & 31;
    // cell-phase mapping: 2 consecutive gate cols per thread
    const int cb  = tid >> 2;          // batch row 0..63
    const int hc0 = (tid & 3) * 2;     // col pair base 0,2,4,6

    // ---- prologue: stage split W slice (aliases h staging), build register frags ----
    {
        __half* Wsh = hSh;                   // [32][520]
        __half* Wsl = Wsh + 32 * HSTR;
        for (int idx = tid; idx < 32 * 512; idx += 256) {
            int c = idx >> 9, k = idx & 511;
            int wrow = (c >> 3) * H_ + j * HS + (c & 7);
            __half hi, lo;
            split_h16(Wh[(size_t)wrow * H_ + k], hi, lo);
            Wsh[c * HSTR + k] = hi;
            Wsl[c * HSTR + k] = lo;
        }
        if (tid < 32)
            bias_s[tid] = bias[(tid >> 3) * H_ + j * HS + (tid & 7)];
        #pragma unroll
        for (int idx = tid; idx < 64 * HS; idx += 256)
            cS[idx] = c0[((size_t)dir * B_ + (idx >> 3)) * H_ + j * HS + (idx & 7)];
        __syncthreads();
    }

    wmma::fragment<wmma::matrix_b, 16, 16, 16, __half, wmma::col_major> bW_h[2][4], bW_l[2][4];
    {
        const __half* Wsh = hSh;
        const __half* Wsl = Wsh + 32 * HSTR;
        #pragma unroll
        for (int j2 = 0; j2 < 2; j2++)
            #pragma unroll
            for (int t4 = 0; t4 < 4; t4++) {
                wmma::load_matrix_sync(bW_h[j2][t4], Wsh + (j2 * 16) * HSTR + w * 64 + t4 * 16, HSTR);
                wmma::load_matrix_sync(bW_l[j2][t4], Wsl + (j2 * 16) * HSTR + w * 64 + t4 * 16, HSTR);
            }
    }
    __syncthreads();   // W staging done; h staging region free

    volatile unsigned* barp = &g_bar[dir][0];

    for (int s = 0; s < T_; ++s) {
        const int cbuf = s & 1;
        const int t = dir ? (T_ - 1 - s) : s;
        const __half* hsrc_h = &g_hh[cbuf][dir][0][0];
        const __half* hsrc_l = &g_hl[cbuf][dir][0][0];
        const float* xpt = xp + (size_t)t * B_ * G_;

        // xg prefetch (independent of h) — issued BEFORE the barrier wait
        float2 xg2[4];
        #pragma unroll
        for (int g = 0; g < 4; g++)
            xg2[g] = *(const float2*)&xpt[(size_t)cb * G_ + g * H_ + j * HS + hc0];

        // wait for all CTAs to have finished step s-1 (h[cbuf] fully written)
        if (s > 0 && tid == 0) {
            unsigned target = (unsigned)s * NCPD;
            while (*barp < target) { }
        }
        __syncthreads();

        // per-warp fill via cp.async.cg (no register round-trip; L2-coherent)
        #pragma unroll
        for (int q = 0; q < 16; q++) {
            int slot = lane + q * 32;
            int r = slot >> 3, c8 = (slot & 7) * 8;
            const int go = r * H_ + w * 64 + c8;
            const int so = r * HSTR + w * 64 + c8;
            cp_async_cg16(&hSh[so], &hsrc_h[go]);
            cp_async_cg16(&hSl[so], &hsrc_l[go]);
        }
        cp_async_commit_wait();
        __syncwarp();

        // MMA on own K-slice (LDSM); store partials to red[w] (stride 40)
        #pragma unroll
        for (int i = 0; i < 4; i++) {
            wmma::fragment<wmma::accumulator, 16, 16, 16, float> am[2], ac[2];
            wmma::fill_fragment(am[0], 0.f); wmma::fill_fragment(am[1], 0.f);
            wmma::fill_fragment(ac[0], 0.f); wmma::fill_fragment(ac[1], 0.f);
            #pragma unroll
            for (int t4 = 0; t4 < 4; t4++) {
                wmma::fragment<wmma::matrix_a, 16, 16, 16, __half, wmma::row_major> a_h, a_l;
                const int off = (i * 16) * HSTR + w * 64 + t4 * 16;
                wmma::load_matrix_sync(a_h, hSh + off, HSTR);
                wmma::load_matrix_sync(a_l, hSl + off, HSTR);
                #pragma unroll
                for (int j2 = 0; j2 < 2; j2++) {
                    wmma::mma_sync(am[j2], a_h, bW_h[j2][t4], am[j2]);
                    wmma::mma_sync(ac[j2], a_l, bW_h[j2][t4], ac[j2]);
                    wmma::mma_sync(ac[j2], a_h, bW_l[j2][t4], ac[j2]);
                }
            }
            #pragma unroll
            for (int j2 = 0; j2 < 2; j2++) {
                #pragma unroll
                for (int e = 0; e < am[j2].num_elements; e++)
                    am[j2].x[e] += ac[j2].x[e] * LO_INV;
                wmma::store_matrix_sync(red + w * (64 * RSTR) + (i * 16) * RSTR + j2 * 16,
                                        am[j2], RSTR, wmma::mem_row_major);
            }
        }
        __syncthreads();   // all partials visible

        // vectorized reduce (float2, conflict-free) + LSTM cell for 2 cols
        __half* hdst_h = &g_hh[cbuf ^ 1][dir][0][0];
        __half* hdst_l = &g_hl[cbuf ^ 1][dir][0][0];
        {
            float2 sum[4];
            #pragma unroll
            for (int g = 0; g < 4; g++) { sum[g].x = 0.f; sum[g].y = 0.f; }
            #pragma unroll
            for (int ww = 0; ww < 8; ww++) {
                const float* rw = red + ww * (64 * RSTR) + cb * RSTR + hc0;
                #pragma unroll
                for (int g = 0; g < 4; g++) {
                    float2 v = *(const float2*)&rw[g * 8];
                    sum[g].x += v.x; sum[g].y += v.y;
                }
            }
            #pragma unroll
            for (int g = 0; g < 4; g++) {
                float2 bsv = *(const float2*)&bias_s[g * 8 + hc0];
                sum[g].x += xg2[g].x + bsv.x;
                sum[g].y += xg2[g].y + bsv.y;
            }
            float2 cold = *(const float2*)&cS[cb * HS + hc0];
            float ii0 = fsig(sum[0].x), ii1 = fsig(sum[0].y);
            float ff0 = fsig(sum[1].x), ff1 = fsig(sum[1].y);
            float gg0 = ftanh(sum[2].x), gg1 = ftanh(sum[2].y);
            float oo0 = fsig(sum[3].x), oo1 = fsig(sum[3].y);
            float cv0 = ff0 * cold.x + ii0 * gg0;
            float cv1 = ff1 * cold.y + ii1 * gg1;
            *(float2*)&cS[cb * HS + hc0] = make_float2(cv0, cv1);
            float hv0 = oo0 * ftanh(cv0);
            float hv1 = oo1 * ftanh(cv1);
            __half h0a, l0a, h1a, l1a;
            split_h16(hv0, h0a, l0a);
            split_h16(hv1, h1a, l1a);
            const int ho = cb * H_ + j * HS + hc0;
            stcg_u32(&hdst_h[ho], h2_bits(h0a, h1a));
            stcg_u32(&hdst_l[ho], h2_bits(l0a, l1a));
            *(float2*)&out[((size_t)t * B_ + cb) * (2 * H_) + dir * H_ + j * HS + hc0] =
                make_float2(hv0, hv1);
        }
        __syncthreads();   // all h stores issued before tid0 releases

        // arrive (release); the wait happens at the top of the next iteration
        if (tid == 0) {
            __threadfence();
            atomicAdd(&g_bar[dir][0], 1u);
        }
    }
}

// ---------------- launch ----------------
extern "C" void kernel_launch(void* const* d_in, const int* in_sizes, int n_in,
                              void* d_out, int out_size)
{
    const float* x    = (const float*)d_in[0];
    const float* h0   = (const float*)d_in[1];
    const float* c0   = (const float*)d_in[2];
    const float* Wihf = (const float*)d_in[3];
    const float* Whhf = (const float*)d_in[4];
    const float* bf   = (const float*)d_in[5];
    const float* Wihb = (const float*)d_in[6];
    const float* Whhb = (const float*)d_in[7];
    const float* bb   = (const float*)d_in[8];
    float* out = (float*)d_out;

    // scan smem: 2*64*520*2 + (8*64*40 + 64*8 + 32)*4 = 217216 B
    cudaFuncSetAttribute(scan_kernel, cudaFuncAttributeMaxDynamicSharedMemorySize, 217216);
    cudaFuncSetAttribute(xproj_kernel, cudaFuncAttributeMaxDynamicSharedMemorySize, 55296);

    dim3 gx(G_ / 64, (T_ * B_) / 128, 2);
    xproj_kernel<<<gx, 256, 55296>>>(x, Wihf, Wihb, h0);

    scan_kernel<<<128, 256, 217216>>>(c0, Whhf, Whhb, bf, bb, out);
}